// round 3
// baseline (speedup 1.0000x reference)
#include <cuda_runtime.h>

#define B_   2
#define H_   12
#define S_   197
#define D_   768
#define HD_  64
#define SS_  (S_*S_)
#define BH_  (B_*H_)
#define LN_EPS 1e-12f

// ---------------- scratch (device globals; no allocation) ----------------
__device__ float g_T[BH_*S_*D_];      // transformed (B,H,S,D)  ~14.5 MB
__device__ float g_tnorm[BH_*S_];     // ||transformed|| per (b,h,s)
__device__ float g_rowsum[B_*S_*D_];  // sum_j summed[b,i,j,d]
__device__ float g_invstd[B_*S_];     // 1/sqrt(var(pre_ln)+eps)

// ---------------- invstd from pre_ln_states ----------------
__global__ void k_invstd(const float* __restrict__ preln)
{
    int row = blockIdx.x;                    // b*S + s
    const float* x = preln + (size_t)row * D_;
    float s = 0.f, s2 = 0.f;
    for (int d = threadIdx.x; d < D_; d += 256) {
        float v = x[d];
        s += v; s2 += v * v;
    }
    #pragma unroll
    for (int o = 16; o; o >>= 1) {
        s  += __shfl_xor_sync(0xffffffffu, s,  o);
        s2 += __shfl_xor_sync(0xffffffffu, s2, o);
    }
    __shared__ float sh0[8], sh1[8];
    if ((threadIdx.x & 31) == 0) { sh0[threadIdx.x >> 5] = s; sh1[threadIdx.x >> 5] = s2; }
    __syncthreads();
    if (threadIdx.x == 0) {
        float S = 0.f, S2 = 0.f;
        #pragma unroll
        for (int w = 0; w < 8; w++) { S += sh0[w]; S2 += sh1[w]; }
        float mean = S * (1.f / D_);
        float var  = S2 * (1.f / D_) - mean * mean;
        g_invstd[row] = rsqrtf(var + LN_EPS);
    }
}

// ---------------- transformed: T[b,h,s,d] = sum_v V[b,h,s,v] * W[d, h*64+v] ----------------
__global__ __launch_bounds__(256)
void k_transformed(const float* __restrict__ V, const float* __restrict__ W)
{
    const int bh = blockIdx.z;
    const int h  = bh % H_;
    const int s0 = blockIdx.x * 32;
    const int d0 = blockIdx.y * 128;
    __shared__ float Vs[64][32];    // [v][s]
    __shared__ float Ws[64][128];   // [v][d]
    const int tid = threadIdx.x;

    for (int idx = tid; idx < 64 * 32; idx += 256) {
        int v = idx >> 5, s = idx & 31;
        int gs = s0 + s;
        Vs[v][s] = (gs < S_) ? V[((size_t)bh * S_ + gs) * HD_ + v] : 0.f;
    }
    for (int idx = tid; idx < 64 * 128; idx += 256) {
        int v = idx >> 7, dd = idx & 127;
        Ws[v][dd] = W[(size_t)(d0 + dd) * D_ + h * HD_ + v];
    }
    __syncthreads();

    const int tx = tid & 31;   // 4 d each -> 128
    const int ty = tid >> 5;   // 8 warps * 4 s -> 32
    float acc[4][4] = {};
    #pragma unroll
    for (int v = 0; v < 64; v++) {
        float4 vv = *(const float4*)&Vs[v][ty * 4];
        float4 ww = *(const float4*)&Ws[v][tx * 4];
        float a[4]  = {vv.x, vv.y, vv.z, vv.w};
        float w4[4] = {ww.x, ww.y, ww.z, ww.w};
        #pragma unroll
        for (int si = 0; si < 4; si++)
            #pragma unroll
            for (int di = 0; di < 4; di++)
                acc[si][di] = fmaf(a[si], w4[di], acc[si][di]);
    }
    #pragma unroll
    for (int si = 0; si < 4; si++) {
        int s = s0 + ty * 4 + si;
        if (s < S_) {
            float4 o = make_float4(acc[si][0], acc[si][1], acc[si][2], acc[si][3]);
            *(float4*)&g_T[((size_t)bh * S_ + s) * D_ + d0 + tx * 4] = o;
        }
    }
}

// ---------------- tnorm[b,h,s] = ||T[b,h,s,:]|| ----------------
__global__ void k_tnorm()
{
    int row = blockIdx.x;                    // bh*S + s
    const float* x = g_T + (size_t)row * D_;
    float s = 0.f;
    for (int d = threadIdx.x; d < D_; d += 256) { float v = x[d]; s += v * v; }
    #pragma unroll
    for (int o = 16; o; o >>= 1) s += __shfl_xor_sync(0xffffffffu, s, o);
    __shared__ float sh[8];
    if ((threadIdx.x & 31) == 0) sh[threadIdx.x >> 5] = s;
    __syncthreads();
    if (threadIdx.x == 0) {
        float t = 0.f;
        #pragma unroll
        for (int w = 0; w < 8; w++) t += sh[w];
        g_tnorm[row] = sqrtf(t);
    }
}

// ---------------- weighted_norm = probs * tnorm (broadcast over first S axis) ----------------
__global__ void k_wnorm(const float* __restrict__ probs, float* __restrict__ wn)
{
    int idx = blockIdx.x * blockDim.x + threadIdx.x;
    if (idx < BH_ * SS_) {
        int bh = idx / SS_;
        int j  = idx % S_;
        wn[idx] = probs[idx] * g_tnorm[bh * S_ + j];
    }
}

// ---------------- rowsum_s[b,i,d] = sum_h sum_j P[b,h,i,j] * T[b,h,j,d] ----------------
__global__ __launch_bounds__(256)
void k_rowsum(const float* __restrict__ P)
{
    const int b  = blockIdx.z;
    const int i0 = blockIdx.x * 32;
    const int d0 = blockIdx.y * 128;
    __shared__ float Ps[32][32];    // [j][i]
    __shared__ float Ts[32][128];   // [j][d]
    const int tid = threadIdx.x;
    const int tx = tid & 31, ty = tid >> 5;
    float acc[4][4] = {};

    for (int h = 0; h < H_; h++) {
        const float* Pb = P   + (size_t)(b * H_ + h) * SS_;
        const float* Tb = g_T + (size_t)(b * H_ + h) * S_ * D_;
        for (int j0 = 0; j0 < S_; j0 += 32) {
            for (int idx = tid; idx < 32 * 32; idx += 256) {
                int jj = idx >> 5, ii = idx & 31;
                int gi = i0 + ii, gj = j0 + jj;
                Ps[jj][ii] = (gi < S_ && gj < S_) ? Pb[(size_t)gi * S_ + gj] : 0.f;
            }
            for (int idx = tid; idx < 32 * 128; idx += 256) {
                int jj = idx >> 7, dd = idx & 127;
                int gj = j0 + jj;
                Ts[jj][dd] = (gj < S_) ? Tb[(size_t)gj * D_ + d0 + dd] : 0.f;
            }
            __syncthreads();
            #pragma unroll 8
            for (int jj = 0; jj < 32; jj++) {
                float4 pp = *(const float4*)&Ps[jj][ty * 4];
                float4 tt = *(const float4*)&Ts[jj][tx * 4];
                float a[4]  = {pp.x, pp.y, pp.z, pp.w};
                float w4[4] = {tt.x, tt.y, tt.z, tt.w};
                #pragma unroll
                for (int si = 0; si < 4; si++)
                    #pragma unroll
                    for (int di = 0; di < 4; di++)
                        acc[si][di] = fmaf(a[si], w4[di], acc[si][di]);
            }
            __syncthreads();
        }
    }
    #pragma unroll
    for (int si = 0; si < 4; si++) {
        int gi = i0 + ty * 4 + si;
        if (gi < S_) {
            float4 o = make_float4(acc[si][0], acc[si][1], acc[si][2], acc[si][3]);
            *(float4*)&g_rowsum[((size_t)(b * S_ + gi)) * D_ + d0 + tx * 4] = o;
        }
    }
}

// ---------------- main fused kernel: block = (b, j), loops i ----------------
// Computes summed_norm, residual_weighted_norm, post_ln_norm, post_ln.
__global__ __launch_bounds__(768, 2)
void k_main(const float* __restrict__ probs, const float* __restrict__ hidden,
            const float* __restrict__ lnw,
            float* __restrict__ o_sn, float* __restrict__ o_rwn,
            float* __restrict__ o_pln, float* __restrict__ o_pl)
{
    const int blk = blockIdx.x;
    const int b = blk / S_, j = blk % S_;
    const int d = threadIdx.x;
    const int lane = d & 31, w = d >> 5;

    float Treg[H_];
    #pragma unroll
    for (int h = 0; h < H_; h++)
        Treg[h] = g_T[((size_t)(b * H_ + h) * S_ + j) * D_ + d];
    const float hreg = hidden[((size_t)(b * S_ + j)) * D_ + d];
    const float lw = lnw[d];
    const float c2 = lw * lw;

    __shared__ float Psh[H_ * S_];   // P[b,h,i,j] over (h,i)
    __shared__ float issh[S_];
    __shared__ float red[5][24];
    __shared__ float bc[8];

    for (int idx = d; idx < H_ * S_; idx += 768) {
        int h = idx / S_, i = idx % S_;
        Psh[idx] = probs[((size_t)(b * H_ + h) * S_ + i) * S_ + j];
    }
    if (d < S_) issh[d] = g_invstd[b * S_ + d];

    // c2sum = sum_d lnw^2 (block-wide constant)
    {
        float v = c2;
        #pragma unroll
        for (int o = 16; o; o >>= 1) v += __shfl_xor_sync(0xffffffffu, v, o);
        if (lane == 0) red[0][w] = v;
        __syncthreads();
        if (d == 0) {
            float s = 0.f;
            #pragma unroll
            for (int k = 0; k < 24; k++) s += red[0][k];
            bc[5] = s;
        }
        __syncthreads();
    }
    const float c2sum = bc[5];

    for (int i = 0; i < S_; i++) {
        float s = 0.f;
        #pragma unroll
        for (int h = 0; h < H_; h++)
            s = fmaf(Psh[h * S_ + i], Treg[h], s);
        float rw = (i == j) ? s + hreg : s;

        float a0 = s * s;          // summed norm^2
        float a1 = rw;             // for each_mean
        float a2 = rw * rw;        // rw norm^2
        float a3 = c2 * rw;        // for analytic pl norm
        float a4 = c2 * rw * rw;

        #pragma unroll
        for (int o = 16; o; o >>= 1) {
            a0 += __shfl_xor_sync(0xffffffffu, a0, o);
            a1 += __shfl_xor_sync(0xffffffffu, a1, o);
            a2 += __shfl_xor_sync(0xffffffffu, a2, o);
            a3 += __shfl_xor_sync(0xffffffffu, a3, o);
            a4 += __shfl_xor_sync(0xffffffffu, a4, o);
        }
        if (lane == 0) {
            red[0][w] = a0; red[1][w] = a1; red[2][w] = a2;
            red[3][w] = a3; red[4][w] = a4;
        }
        __syncthreads();
        if (d < 5) {
            float sum = 0.f;
            #pragma unroll
            for (int k = 0; k < 24; k++) sum += red[d][k];
            bc[d] = sum;
        }
        __syncthreads();
        float S1 = bc[1];
        float mean = S1 * (1.f / D_);
        float is = issh[i];
        float pl = (rw - mean) * is * lw;
        o_pl[((size_t)(b * S_ + i) * S_ + j) * D_ + d] = pl;
        if (d == 0) {
            int oidx = (b * S_ + i) * S_ + j;
            o_sn[oidx]  = sqrtf(bc[0]);
            o_rwn[oidx] = sqrtf(bc[2]);
            float pn2 = is * is * (bc[4] - 2.f * mean * bc[3] + mean * mean * c2sum);
            o_pln[oidx] = sqrtf(fmaxf(pn2, 0.f));
        }
    }
}

// ---------------- mixing ratios: block = (b, i) ----------------
__global__ __launch_bounds__(768)
void k_mix(const float* __restrict__ probs, const float* __restrict__ hidden,
           const float* __restrict__ lnw,
           float* __restrict__ m1, float* __restrict__ m2, float* __restrict__ m3)
{
    const int blk = blockIdx.x;
    const int b = blk / S_, i = blk % S_;
    const int d = threadIdx.x;
    const int lane = d & 31, w = d >> 5;

    __shared__ float Pd[H_];
    __shared__ float red[5][24];
    __shared__ float bc[8];
    if (d < H_) Pd[d] = probs[((size_t)(b * H_ + d) * S_ + i) * S_ + i];
    __syncthreads();

    float sii = 0.f;
    #pragma unroll
    for (int h = 0; h < H_; h++)
        sii = fmaf(Pd[h], g_T[((size_t)(b * H_ + h) * S_ + i) * D_ + d], sii);

    float rs   = g_rowsum[((size_t)(b * S_ + i)) * D_ + d];
    float hd   = hidden [((size_t)(b * S_ + i)) * D_ + d];
    float lw   = lnw[d];
    float mixv = rs - sii;       // mixing vector (same for summed & residual_weighted)
    float rwii = sii + hd;       // diagonal of residual_weighted
    float rsrw = rs + hd;        // sum_j residual_weighted

    float a0 = mixv * mixv;      // mn1^2
    float a1 = sii * sii;        // pn1^2
    float a2 = rwii * rwii;      // pn2^2
    float a3 = rwii;             // -> mean_ii
    float a4 = rsrw;             // -> M

    #pragma unroll
    for (int o = 16; o; o >>= 1) {
        a0 += __shfl_xor_sync(0xffffffffu, a0, o);
        a1 += __shfl_xor_sync(0xffffffffu, a1, o);
        a2 += __shfl_xor_sync(0xffffffffu, a2, o);
        a3 += __shfl_xor_sync(0xffffffffu, a3, o);
        a4 += __shfl_xor_sync(0xffffffffu, a4, o);
    }
    if (lane == 0) {
        red[0][w] = a0; red[1][w] = a1; red[2][w] = a2;
        red[3][w] = a3; red[4][w] = a4;
    }
    __syncthreads();
    if (d < 5) {
        float sum = 0.f;
        #pragma unroll
        for (int k = 0; k < 24; k++) sum += red[d][k];
        bc[d] = sum;
    }
    __syncthreads();
    float mn1sq = bc[0], pn1sq = bc[1], pn2sq = bc[2];
    float mean_ii = bc[3] * (1.f / D_);
    float M       = bc[4] * (1.f / D_);
    float is = g_invstd[b * S_ + i];

    float pres3 = (rwii - mean_ii) * is * lw;          // diag of post_ln
    float mix3  = is * lw * (rsrw - M) - pres3;        // sum_j post_ln - diag
    float b0 = pres3 * pres3, b1 = mix3 * mix3;
    #pragma unroll
    for (int o = 16; o; o >>= 1) {
        b0 += __shfl_xor_sync(0xffffffffu, b0, o);
        b1 += __shfl_xor_sync(0xffffffffu, b1, o);
    }
    if (lane == 0) { red[0][w] = b0; red[1][w] = b1; }
    __syncthreads();
    if (d == 0) {
        float B0 = 0.f, B1 = 0.f;
        #pragma unroll
        for (int k = 0; k < 24; k++) { B0 += red[0][k]; B1 += red[1][k]; }
        float mn1 = sqrtf(mn1sq), pn1 = sqrtf(pn1sq), pn2 = sqrtf(pn2sq);
        float pn3 = sqrtf(B0),   mn3 = sqrtf(B1);
        m1[b * S_ + i] = mn1 / (mn1 + pn1);
        m2[b * S_ + i] = mn1 / (mn1 + pn2);
        m3[b * S_ + i] = mn3 / (mn3 + pn3);
    }
}

// ---------------- launch ----------------
extern "C" void kernel_launch(void* const* d_in, const int* in_sizes, int n_in,
                              void* d_out, int out_size)
{
    const float* hidden = (const float*)d_in[0];
    const float* probs  = (const float*)d_in[1];
    const float* value  = (const float*)d_in[2];
    const float* dw     = (const float*)d_in[3];
    const float* lnw    = (const float*)d_in[4];
    const float* preln  = (const float*)d_in[5];

    float* out   = (float*)d_out;
    float* o_wn  = out;                                   // (B,H,S,S)
    float* o_sn  = o_wn  + (size_t)BH_ * SS_;             // (B,S,S)
    float* o_rwn = o_sn  + (size_t)B_ * SS_;              // (B,S,S)
    float* o_pln = o_rwn + (size_t)B_ * SS_;              // (B,S,S)
    float* o_pl  = o_pln + (size_t)B_ * SS_;              // (B,S,S,D)
    float* o_m1  = o_pl  + (size_t)B_ * SS_ * D_;         // (B,S)
    float* o_m2  = o_m1  + B_ * S_;
    float* o_m3  = o_m2  + B_ * S_;

    k_invstd<<<B_ * S_, 256>>>(preln);
    k_transformed<<<dim3(7, 6, BH_), 256>>>(value, dw);
    k_tnorm<<<BH_ * S_, 256>>>();
    k_wnorm<<<(BH_ * SS_ + 255) / 256, 256>>>(probs, o_wn);
    k_rowsum<<<dim3(7, 6, B_), 256>>>(probs);
    k_main<<<B_ * S_, 768>>>(probs, hidden, lnw, o_sn, o_rwn, o_pln, o_pl);
    k_mix<<<B_ * S_, 768>>>(probs, hidden, lnw, o_m1, o_m2, o_m3);
}

// round 6
// speedup vs baseline: 1.8147x; 1.8147x over previous
#include <cuda_runtime.h>

#define B_   2
#define H_   12
#define S_   197
#define D_   768
#define HD_  64
#define SS_  (S_*S_)
#define BH_  (B_*H_)
#define LN_EPS 1e-12f
#define NPAIR 78          // 12*13/2
#define NDOT  209         // 78 G1 + 78 G2 + 4*12 vecs + 5 scalars

// ---------------- scratch (device globals; no allocation) ----------------
__device__ __align__(16) float g_T[BH_*S_*D_];      // transformed (B,H,S,D)
__device__ __align__(16) float g_tnorm[BH_*S_];     // ||transformed|| per (b,h,s)
__device__ __align__(16) float g_rowsum[B_*S_*D_];  // sum_j summed[b,i,j,d]
__device__ __align__(16) float g_invstd[B_*S_];     // 1/sqrt(var(pre_ln)+eps)
__device__ __align__(16) float g_mean[B_*SS_];      // each_mean[b,i,j]

__device__ __forceinline__ float wred(float x) {
    #pragma unroll
    for (int o = 16; o; o >>= 1) x += __shfl_xor_sync(0xffffffffu, x, o);
    return x;
}

// ---------------- invstd from pre_ln_states ----------------
__global__ void k_invstd(const float* __restrict__ preln)
{
    int row = blockIdx.x;
    const float* x = preln + (size_t)row * D_;
    float s = 0.f, s2 = 0.f;
    for (int d = threadIdx.x; d < D_; d += 256) {
        float v = x[d];
        s += v; s2 += v * v;
    }
    s = wred(s); s2 = wred(s2);
    __shared__ float sh0[8], sh1[8];
    if ((threadIdx.x & 31) == 0) { sh0[threadIdx.x >> 5] = s; sh1[threadIdx.x >> 5] = s2; }
    __syncthreads();
    if (threadIdx.x == 0) {
        float S = 0.f, S2 = 0.f;
        #pragma unroll
        for (int w = 0; w < 8; w++) { S += sh0[w]; S2 += sh1[w]; }
        float mean = S * (1.f / D_);
        float var  = S2 * (1.f / D_) - mean * mean;
        g_invstd[row] = rsqrtf(var + LN_EPS);
    }
}

// ---------------- transformed: T[b,h,s,d] = sum_v V[b,h,s,v] * W[d, h*64+v] ----------------
__global__ __launch_bounds__(256)
void k_transformed(const float* __restrict__ V, const float* __restrict__ W)
{
    const int bh = blockIdx.z;
    const int h  = bh % H_;
    const int s0 = blockIdx.x * 32;
    const int d0 = blockIdx.y * 128;
    __shared__ __align__(16) float Vs[64][32];
    __shared__ __align__(16) float Ws[64][128];
    const int tid = threadIdx.x;

    for (int idx = tid; idx < 64 * 32; idx += 256) {
        int v = idx >> 5, s = idx & 31;
        int gs = s0 + s;
        Vs[v][s] = (gs < S_) ? V[((size_t)bh * S_ + gs) * HD_ + v] : 0.f;
    }
    for (int idx = tid; idx < 64 * 128; idx += 256) {
        int v = idx >> 7, dd = idx & 127;
        Ws[v][dd] = W[(size_t)(d0 + dd) * D_ + h * HD_ + v];
    }
    __syncthreads();

    const int tx = tid & 31;
    const int ty = tid >> 5;
    float acc[4][4] = {};
    #pragma unroll
    for (int v = 0; v < 64; v++) {
        float4 vv = *(const float4*)&Vs[v][ty * 4];
        float4 ww = *(const float4*)&Ws[v][tx * 4];
        float a[4]  = {vv.x, vv.y, vv.z, vv.w};
        float w4[4] = {ww.x, ww.y, ww.z, ww.w};
        #pragma unroll
        for (int si = 0; si < 4; si++)
            #pragma unroll
            for (int di = 0; di < 4; di++)
                acc[si][di] = fmaf(a[si], w4[di], acc[si][di]);
    }
    #pragma unroll
    for (int si = 0; si < 4; si++) {
        int s = s0 + ty * 4 + si;
        if (s < S_) {
            float4 o = make_float4(acc[si][0], acc[si][1], acc[si][2], acc[si][3]);
            *(float4*)&g_T[((size_t)bh * S_ + s) * D_ + d0 + tx * 4] = o;
        }
    }
}

// ---------------- scalar kernel: Gram matrices + all per-(i,j) scalars ----------------
__global__ __launch_bounds__(256)
void k_scal(const float* __restrict__ probs, const float* __restrict__ hidden,
            const float* __restrict__ lnw,
            float* __restrict__ o_sn, float* __restrict__ o_rwn,
            float* __restrict__ o_pln)
{
    const int j = blockIdx.x, b = blockIdx.y;
    const int tid = threadIdx.x;
    const int lane = tid & 31, w = tid >> 5;

    __shared__ float part[NDOT * 8];
    __shared__ float dsm[NDOT];
    __shared__ float Psh[S_ * 13];   // [i][h], stride 13 to dodge bank conflicts

    float T[12][3], hd[3], c2[3];
    #pragma unroll
    for (int h = 0; h < 12; h++) {
        const float* tp = g_T + ((size_t)(b * H_ + h) * S_ + j) * D_ + tid;
        #pragma unroll
        for (int k = 0; k < 3; k++) T[h][k] = tp[k * 256];
    }
    {
        const float* hp = hidden + ((size_t)(b * S_ + j)) * D_ + tid;
        const float* cp = lnw + tid;
        #pragma unroll
        for (int k = 0; k < 3; k++) {
            hd[k] = hp[k * 256];
            float c = cp[k * 256];
            c2[k] = c * c;
        }
    }

    for (int idx = tid; idx < H_ * S_; idx += 256) {
        int i = idx / 12, h = idx % 12;
        Psh[i * 13 + h] = probs[((size_t)(b * H_ + h) * S_ + i) * S_ + j];
    }

    // --- Gram pairs: G1[p], G2[p] ---
    {
        int p = 0;
        #pragma unroll
        for (int h = 0; h < 12; h++) {
            #pragma unroll
            for (int h2 = h; h2 < 12; h2++) {
                float q0 = T[h][0] * T[h2][0];
                float q1 = T[h][1] * T[h2][1];
                float q2 = T[h][2] * T[h2][2];
                float g1 = q0 + q1 + q2;
                float g2 = c2[0] * q0 + c2[1] * q1 + c2[2] * q2;
                g1 = wred(g1); g2 = wred(g2);
                if (lane == 0) {
                    part[p * 8 + w]           = g1;
                    part[(NPAIR + p) * 8 + w] = g2;
                }
                p++;
            }
        }
    }
    // --- vectors u1,u2,v1,v2 ---
    #pragma unroll
    for (int h = 0; h < 12; h++) {
        float u1 = T[h][0] + T[h][1] + T[h][2];
        float u2 = c2[0] * T[h][0] + c2[1] * T[h][1] + c2[2] * T[h][2];
        float q0 = T[h][0] * hd[0], q1 = T[h][1] * hd[1], q2 = T[h][2] * hd[2];
        float v1 = q0 + q1 + q2;
        float v2 = c2[0] * q0 + c2[1] * q1 + c2[2] * q2;
        u1 = wred(u1); u2 = wred(u2); v1 = wred(v1); v2 = wred(v2);
        if (lane == 0) {
            part[(156 + h) * 8 + w] = u1;
            part[(168 + h) * 8 + w] = u2;
            part[(180 + h) * 8 + w] = v1;
            part[(192 + h) * 8 + w] = v2;
        }
    }
    // --- scalars e0..e3, c2sum ---
    {
        float e0 = 0.f, e1 = 0.f, e2 = 0.f, e3 = 0.f, cs = 0.f;
        #pragma unroll
        for (int k = 0; k < 3; k++) {
            e0 += hd[k] * hd[k];
            e1 += hd[k];
            e2 += c2[k] * hd[k];
            e3 += c2[k] * hd[k] * hd[k];
            cs += c2[k];
        }
        e0 = wred(e0); e1 = wred(e1); e2 = wred(e2); e3 = wred(e3); cs = wred(cs);
        if (lane == 0) {
            part[204 * 8 + w] = e0; part[205 * 8 + w] = e1;
            part[206 * 8 + w] = e2; part[207 * 8 + w] = e3;
            part[208 * 8 + w] = cs;
        }
    }
    __syncthreads();
    if (tid < NDOT) {
        float s = 0.f;
        #pragma unroll
        for (int k = 0; k < 8; k++) s += part[tid * 8 + k];
        dsm[tid] = s;
    }
    __syncthreads();

    if (tid < 12) {
        int h = tid;
        int pd = h * 12 - (h * (h - 1)) / 2;
        g_tnorm[(b * H_ + h) * S_ + j] = sqrtf(fmaxf(dsm[pd], 0.f));
    }

    if (tid < S_) {
        int i = tid;
        float P[12];
        #pragma unroll
        for (int h = 0; h < 12; h++) P[h] = Psh[i * 13 + h];

        float n1 = 0.f, n3 = 0.f;
        {
            int p = 0;
            #pragma unroll
            for (int h = 0; h < 12; h++) {
                float ph = P[h];
                n1 = fmaf(ph * ph, dsm[p], n1);
                n3 = fmaf(ph * ph, dsm[NPAIR + p], n3);
                p++;
                #pragma unroll
                for (int h2 = h + 1; h2 < 12; h2++) {
                    float pp = 2.f * ph * P[h2];
                    n1 = fmaf(pp, dsm[p], n1);
                    n3 = fmaf(pp, dsm[NPAIR + p], n3);
                    p++;
                }
            }
        }
        float sum_s = 0.f, L = 0.f, sv1 = 0.f, sv2 = 0.f;
        #pragma unroll
        for (int h = 0; h < 12; h++) {
            sum_s = fmaf(P[h], dsm[156 + h], sum_s);
            L     = fmaf(P[h], dsm[168 + h], L);
            sv1   = fmaf(P[h], dsm[180 + h], sv1);
            sv2   = fmaf(P[h], dsm[192 + h], sv2);
        }
        float n2 = n1, Ssum = sum_s, a3 = L, a4 = n3;
        if (i == j) {
            n2   += 2.f * sv1 + dsm[204];
            Ssum += dsm[205];
            a3   += dsm[206];
            a4   += 2.f * sv2 + dsm[207];
        }
        float mean = Ssum * (1.f / D_);
        float is = g_invstd[b * S_ + i];
        int o = (b * S_ + i) * S_ + j;
        o_sn[o]  = sqrtf(fmaxf(n1, 0.f));
        o_rwn[o] = sqrtf(fmaxf(n2, 0.f));
        float pn2 = is * is * (a4 - 2.f * mean * a3 + mean * mean * dsm[208]);
        o_pln[o] = sqrtf(fmaxf(pn2, 0.f));
        g_mean[o] = mean;
    }
}

// ---------------- weighted_norm = probs * tnorm ----------------
__global__ void k_wnorm(const float* __restrict__ probs, float* __restrict__ wn)
{
    int idx = blockIdx.x * blockDim.x + threadIdx.x;
    if (idx < BH_ * SS_) {
        int bh = idx / SS_;
        int j  = idx % S_;
        wn[idx] = probs[idx] * g_tnorm[bh * S_ + j];
    }
}

// ---------------- rowsum_s[b,i,d] = sum_h sum_j P[b,h,i,j] * T[b,h,j,d] ----------------
__global__ __launch_bounds__(256)
void k_rowsum(const float* __restrict__ P)
{
    const int b  = blockIdx.z;
    const int i0 = blockIdx.x * 32;
    const int d0 = blockIdx.y * 128;
    __shared__ __align__(16) float Ps[32][32];
    __shared__ __align__(16) float Ts[32][128];
    const int tid = threadIdx.x;
    const int tx = tid & 31, ty = tid >> 5;
    float acc[4][4] = {};

    for (int h = 0; h < H_; h++) {
        const float* Pb = P   + (size_t)(b * H_ + h) * SS_;
        const float* Tb = g_T + (size_t)(b * H_ + h) * S_ * D_;
        for (int j0 = 0; j0 < S_; j0 += 32) {
            for (int idx = tid; idx < 32 * 32; idx += 256) {
                int jj = idx >> 5, ii = idx & 31;
                int gi = i0 + ii, gj = j0 + jj;
                Ps[jj][ii] = (gi < S_ && gj < S_) ? Pb[(size_t)gi * S_ + gj] : 0.f;
            }
            for (int idx = tid; idx < 32 * 128; idx += 256) {
                int jj = idx >> 7, dd = idx & 127;
                int gj = j0 + jj;
                Ts[jj][dd] = (gj < S_) ? Tb[(size_t)gj * D_ + d0 + dd] : 0.f;
            }
            __syncthreads();
            #pragma unroll 8
            for (int jj = 0; jj < 32; jj++) {
                float4 pp = *(const float4*)&Ps[jj][ty * 4];
                float4 tt = *(const float4*)&Ts[jj][tx * 4];
                float a[4]  = {pp.x, pp.y, pp.z, pp.w};
                float w4[4] = {tt.x, tt.y, tt.z, tt.w};
                #pragma unroll
                for (int si = 0; si < 4; si++)
                    #pragma unroll
                    for (int di = 0; di < 4; di++)
                        acc[si][di] = fmaf(a[si], w4[di], acc[si][di]);
            }
            __syncthreads();
        }
    }
    #pragma unroll
    for (int si = 0; si < 4; si++) {
        int gi = i0 + ty * 4 + si;
        if (gi < S_) {
            float4 o = make_float4(acc[si][0], acc[si][1], acc[si][2], acc[si][3]);
            *(float4*)&g_rowsum[((size_t)(b * S_ + gi)) * D_ + d0 + tx * 4] = o;
        }
    }
}

// ---------------- post_ln elementwise: block = (j, b, half), 192 thr x 4 d ----------------
// NOTE: o_pl's byte offset within d_out is only 8B-aligned -> use float2 stores.
__global__ __launch_bounds__(192)
void k_pl(const float* __restrict__ probs, const float* __restrict__ hidden,
          const float* __restrict__ lnw, float* __restrict__ o_pl)
{
    const int j = blockIdx.x, b = blockIdx.y, half = blockIdx.z;
    const int tid = threadIdx.x;
    const int d0 = tid * 4;

    float4 Tv[12];
    #pragma unroll
    for (int h = 0; h < 12; h++)
        Tv[h] = *(const float4*)&g_T[((size_t)(b * H_ + h) * S_ + j) * D_ + d0];
    const float4 hv = *(const float4*)&hidden[((size_t)(b * S_ + j)) * D_ + d0];
    const float4 cv = *(const float4*)&lnw[d0];

    __shared__ __align__(16) float Psh[S_ * 12];  // [i][h] contiguous
    __shared__ float msh[S_], ish[S_];

    for (int idx = tid; idx < H_ * S_; idx += 192) {
        int i = idx / 12, h = idx % 12;
        Psh[idx] = probs[((size_t)(b * H_ + h) * S_ + i) * S_ + j];
    }
    for (int t = tid; t < S_; t += 192) {
        msh[t] = g_mean[(b * S_ + t) * S_ + j];
        ish[t] = g_invstd[b * S_ + t];
    }
    __syncthreads();

    const int i0 = half ? 99 : 0;
    const int i1 = half ? S_ : 99;
    for (int i = i0; i < i1; i++) {
        const float4* Pp = (const float4*)&Psh[i * 12];
        float4 p0 = Pp[0], p1 = Pp[1], p2 = Pp[2];
        float P[12] = {p0.x, p0.y, p0.z, p0.w, p1.x, p1.y, p1.z, p1.w,
                       p2.x, p2.y, p2.z, p2.w};
        float4 s = make_float4(0.f, 0.f, 0.f, 0.f);
        #pragma unroll
        for (int h = 0; h < 12; h++) {
            s.x = fmaf(P[h], Tv[h].x, s.x);
            s.y = fmaf(P[h], Tv[h].y, s.y);
            s.z = fmaf(P[h], Tv[h].z, s.z);
            s.w = fmaf(P[h], Tv[h].w, s.w);
        }
        if (i == j) { s.x += hv.x; s.y += hv.y; s.z += hv.z; s.w += hv.w; }
        float m = msh[i], is = ish[i];
        float2 oa, ob;
        oa.x = (s.x - m) * is * cv.x;
        oa.y = (s.y - m) * is * cv.y;
        ob.x = (s.z - m) * is * cv.z;
        ob.y = (s.w - m) * is * cv.w;
        float* dst = &o_pl[((size_t)(b * S_ + i) * S_ + j) * D_ + d0];
        *(float2*)(dst)     = oa;   // 8B-aligned: safe
        *(float2*)(dst + 2) = ob;
    }
}

// ---------------- mixing ratios: block = (b, i) ----------------
__global__ __launch_bounds__(768)
void k_mix(const float* __restrict__ probs, const float* __restrict__ hidden,
           const float* __restrict__ lnw,
           float* __restrict__ m1, float* __restrict__ m2, float* __restrict__ m3)
{
    const int blk = blockIdx.x;
    const int b = blk / S_, i = blk % S_;
    const int d = threadIdx.x;
    const int lane = d & 31, w = d >> 5;

    __shared__ float Pd[H_];
    __shared__ float red[5][24];
    __shared__ float bc[8];
    if (d < H_) Pd[d] = probs[((size_t)(b * H_ + d) * S_ + i) * S_ + i];
    __syncthreads();

    float sii = 0.f;
    #pragma unroll
    for (int h = 0; h < H_; h++)
        sii = fmaf(Pd[h], g_T[((size_t)(b * H_ + h) * S_ + i) * D_ + d], sii);

    float rs   = g_rowsum[((size_t)(b * S_ + i)) * D_ + d];
    float hd   = hidden [((size_t)(b * S_ + i)) * D_ + d];
    float lw   = lnw[d];
    float mixv = rs - sii;
    float rwii = sii + hd;
    float rsrw = rs + hd;

    float a0 = wred(mixv * mixv);
    float a1 = wred(sii * sii);
    float a2 = wred(rwii * rwii);
    float a3 = wred(rwii);
    float a4 = wred(rsrw);
    if (lane == 0) {
        red[0][w] = a0; red[1][w] = a1; red[2][w] = a2;
        red[3][w] = a3; red[4][w] = a4;
    }
    __syncthreads();
    if (d < 5) {
        float sum = 0.f;
        #pragma unroll
        for (int k = 0; k < 24; k++) sum += red[d][k];
        bc[d] = sum;
    }
    __syncthreads();
    float mn1sq = bc[0], pn1sq = bc[1], pn2sq = bc[2];
    float mean_ii = bc[3] * (1.f / D_);
    float M       = bc[4] * (1.f / D_);
    float is = g_invstd[b * S_ + i];

    float pres3 = (rwii - mean_ii) * is * lw;
    float mix3  = is * lw * (rsrw - M) - pres3;
    float b0 = wred(pres3 * pres3);
    float b1 = wred(mix3 * mix3);
    if (lane == 0) { red[0][w] = b0; red[1][w] = b1; }
    __syncthreads();
    if (d == 0) {
        float B0 = 0.f, B1 = 0.f;
        #pragma unroll
        for (int k = 0; k < 24; k++) { B0 += red[0][k]; B1 += red[1][k]; }
        float mn1 = sqrtf(mn1sq), pn1 = sqrtf(pn1sq), pn2 = sqrtf(pn2sq);
        float pn3 = sqrtf(B0),   mn3 = sqrtf(B1);
        m1[b * S_ + i] = mn1 / (mn1 + pn1);
        m2[b * S_ + i] = mn1 / (mn1 + pn2);
        m3[b * S_ + i] = mn3 / (mn3 + pn3);
    }
}

// ---------------- launch ----------------
extern "C" void kernel_launch(void* const* d_in, const int* in_sizes, int n_in,
                              void* d_out, int out_size)
{
    const float* hidden = (const float*)d_in[0];
    const float* probs  = (const float*)d_in[1];
    const float* value  = (const float*)d_in[2];
    const float* dw     = (const float*)d_in[3];
    const float* lnw    = (const float*)d_in[4];
    const float* preln  = (const float*)d_in[5];

    float* out   = (float*)d_out;
    float* o_wn  = out;                                   // (B,H,S,S)
    float* o_sn  = o_wn  + (size_t)BH_ * SS_;             // (B,S,S)
    float* o_rwn = o_sn  + (size_t)B_ * SS_;              // (B,S,S)
    float* o_pln = o_rwn + (size_t)B_ * SS_;              // (B,S,S)
    float* o_pl  = o_pln + (size_t)B_ * SS_;              // (B,S,S,D)
    float* o_m1  = o_pl  + (size_t)B_ * SS_ * D_;         // (B,S)
    float* o_m2  = o_m1  + B_ * S_;
    float* o_m3  = o_m2  + B_ * S_;

    k_invstd<<<B_ * S_, 256>>>(preln);
    k_transformed<<<dim3(7, 6, BH_), 256>>>(value, dw);
    k_scal<<<dim3(S_, B_), 256>>>(probs, hidden, lnw, o_sn, o_rwn, o_pln);
    k_wnorm<<<(BH_ * SS_ + 255) / 256, 256>>>(probs, o_wn);
    k_rowsum<<<dim3(7, 6, B_), 256>>>(probs);
    k_pl<<<dim3(S_, B_, 2), 192>>>(probs, hidden, lnw, o_pl);
    k_mix<<<B_ * S_, 768>>>(probs, hidden, lnw, o_m1, o_m2, o_m3);
}

// round 7
// speedup vs baseline: 2.9480x; 1.6245x over previous
#include <cuda_runtime.h>

#define B_   2
#define H_   12
#define S_   197
#define D_   768
#define HD_  64
#define SS_  (S_*S_)
#define BH_  (B_*H_)
#define LN_EPS 1e-12f
#define NPAIR 78
#define NDOT  209
#define KS_   4            // k-split for rowsum (3 heads each)

typedef unsigned long long ull;

// ---------------- scratch (device globals; no allocation) ----------------
__device__ __align__(16) float g_T[BH_*S_*D_];
__device__ __align__(16) float g_tnorm[BH_*S_];
__device__ __align__(16) float g_rs4[KS_][B_*S_*D_];   // rowsum partials
__device__ __align__(16) float g_invstd[B_*S_];
__device__ __align__(16) float g_mean[B_*SS_];

__device__ __forceinline__ float wred(float x) {
    #pragma unroll
    for (int o = 16; o; o >>= 1) x += __shfl_xor_sync(0xffffffffu, x, o);
    return x;
}

// ---- packed f32x2 helpers (Blackwell FFMA2 via PTX) ----
__device__ __forceinline__ ull pack2(float lo, float hi) {
    ull r;
    asm("mov.b64 %0, {%1, %2};" : "=l"(r) : "f"(lo), "f"(hi));
    return r;
}
__device__ __forceinline__ void fma2(ull& d, ull a, ull b) {
    asm("fma.rn.f32x2 %0, %1, %2, %0;" : "+l"(d) : "l"(a), "l"(b));
}
__device__ __forceinline__ float2 unpack2(ull v) {
    float2 f;
    asm("mov.b64 {%0, %1}, %2;" : "=f"(f.x), "=f"(f.y) : "l"(v));
    return f;
}

// ---------------- invstd from pre_ln_states ----------------
__global__ void k_invstd(const float* __restrict__ preln)
{
    int row = blockIdx.x;
    const float* x = preln + (size_t)row * D_;
    float s = 0.f, s2 = 0.f;
    for (int d = threadIdx.x; d < D_; d += 256) {
        float v = x[d];
        s += v; s2 += v * v;
    }
    s = wred(s); s2 = wred(s2);
    __shared__ float sh0[8], sh1[8];
    if ((threadIdx.x & 31) == 0) { sh0[threadIdx.x >> 5] = s; sh1[threadIdx.x >> 5] = s2; }
    __syncthreads();
    if (threadIdx.x == 0) {
        float S = 0.f, S2 = 0.f;
        #pragma unroll
        for (int w = 0; w < 8; w++) { S += sh0[w]; S2 += sh1[w]; }
        float mean = S * (1.f / D_);
        float var  = S2 * (1.f / D_) - mean * mean;
        g_invstd[row] = rsqrtf(var + LN_EPS);
    }
}

// ---------------- transformed: T[b,h,s,d] = sum_v V[b,h,s,v] * W[d, h*64+v] ----------------
__global__ __launch_bounds__(256)
void k_transformed(const float* __restrict__ V, const float* __restrict__ W)
{
    const int bh = blockIdx.z;
    const int h  = bh % H_;
    const int s0 = blockIdx.x * 32;
    const int d0 = blockIdx.y * 128;
    __shared__ __align__(16) float Vs[64][32];
    __shared__ __align__(16) float Ws[64][128];
    const int tid = threadIdx.x;

    for (int idx = tid; idx < 64 * 32; idx += 256) {
        int v = idx >> 5, s = idx & 31;
        int gs = s0 + s;
        Vs[v][s] = (gs < S_) ? V[((size_t)bh * S_ + gs) * HD_ + v] : 0.f;
    }
    for (int idx = tid; idx < 64 * 128; idx += 256) {
        int v = idx >> 7, dd = idx & 127;
        Ws[v][dd] = W[(size_t)(d0 + dd) * D_ + h * HD_ + v];
    }
    __syncthreads();

    const int tx = tid & 31;
    const int ty = tid >> 5;
    ull acc[4][2] = {};
    #pragma unroll
    for (int v = 0; v < 64; v++) {
        float4 vv = *(const float4*)&Vs[v][ty * 4];
        float4 ww = *(const float4*)&Ws[v][tx * 4];
        ull t01 = pack2(ww.x, ww.y), t23 = pack2(ww.z, ww.w);
        ull a0 = pack2(vv.x, vv.x), a1 = pack2(vv.y, vv.y);
        ull a2 = pack2(vv.z, vv.z), a3 = pack2(vv.w, vv.w);
        fma2(acc[0][0], a0, t01); fma2(acc[0][1], a0, t23);
        fma2(acc[1][0], a1, t01); fma2(acc[1][1], a1, t23);
        fma2(acc[2][0], a2, t01); fma2(acc[2][1], a2, t23);
        fma2(acc[3][0], a3, t01); fma2(acc[3][1], a3, t23);
    }
    #pragma unroll
    for (int si = 0; si < 4; si++) {
        int s = s0 + ty * 4 + si;
        if (s < S_) {
            float2 lo = unpack2(acc[si][0]), hi = unpack2(acc[si][1]);
            float4 o = make_float4(lo.x, lo.y, hi.x, hi.y);
            *(float4*)&g_T[((size_t)bh * S_ + s) * D_ + d0 + tx * 4] = o;
        }
    }
}

// ---------------- scalar kernel: Gram matrices + all per-(i,j) scalars ----------------
__global__ __launch_bounds__(256)
void k_scal(const float* __restrict__ probs, const float* __restrict__ hidden,
            const float* __restrict__ lnw,
            float* __restrict__ o_sn, float* __restrict__ o_rwn,
            float* __restrict__ o_pln)
{
    const int j = blockIdx.x, b = blockIdx.y;
    const int tid = threadIdx.x;
    const int lane = tid & 31, w = tid >> 5;

    __shared__ float part[NDOT * 8];
    __shared__ float dsm[NDOT];
    __shared__ float Psh[S_ * 13];

    float T[12][3], hd[3], c2[3];
    #pragma unroll
    for (int h = 0; h < 12; h++) {
        const float* tp = g_T + ((size_t)(b * H_ + h) * S_ + j) * D_ + tid;
        #pragma unroll
        for (int k = 0; k < 3; k++) T[h][k] = tp[k * 256];
    }
    {
        const float* hp = hidden + ((size_t)(b * S_ + j)) * D_ + tid;
        const float* cp = lnw + tid;
        #pragma unroll
        for (int k = 0; k < 3; k++) {
            hd[k] = hp[k * 256];
            float c = cp[k * 256];
            c2[k] = c * c;
        }
    }

    for (int idx = tid; idx < H_ * S_; idx += 256) {
        int i = idx / 12, h = idx % 12;
        Psh[i * 13 + h] = probs[((size_t)(b * H_ + h) * S_ + i) * S_ + j];
    }

    {
        int p = 0;
        #pragma unroll
        for (int h = 0; h < 12; h++) {
            #pragma unroll
            for (int h2 = h; h2 < 12; h2++) {
                float q0 = T[h][0] * T[h2][0];
                float q1 = T[h][1] * T[h2][1];
                float q2 = T[h][2] * T[h2][2];
                float g1 = q0 + q1 + q2;
                float g2 = c2[0] * q0 + c2[1] * q1 + c2[2] * q2;
                g1 = wred(g1); g2 = wred(g2);
                if (lane == 0) {
                    part[p * 8 + w]           = g1;
                    part[(NPAIR + p) * 8 + w] = g2;
                }
                p++;
            }
        }
    }
    #pragma unroll
    for (int h = 0; h < 12; h++) {
        float u1 = T[h][0] + T[h][1] + T[h][2];
        float u2 = c2[0] * T[h][0] + c2[1] * T[h][1] + c2[2] * T[h][2];
        float q0 = T[h][0] * hd[0], q1 = T[h][1] * hd[1], q2 = T[h][2] * hd[2];
        float v1 = q0 + q1 + q2;
        float v2 = c2[0] * q0 + c2[1] * q1 + c2[2] * q2;
        u1 = wred(u1); u2 = wred(u2); v1 = wred(v1); v2 = wred(v2);
        if (lane == 0) {
            part[(156 + h) * 8 + w] = u1;
            part[(168 + h) * 8 + w] = u2;
            part[(180 + h) * 8 + w] = v1;
            part[(192 + h) * 8 + w] = v2;
        }
    }
    {
        float e0 = 0.f, e1 = 0.f, e2 = 0.f, e3 = 0.f, cs = 0.f;
        #pragma unroll
        for (int k = 0; k < 3; k++) {
            e0 += hd[k] * hd[k];
            e1 += hd[k];
            e2 += c2[k] * hd[k];
            e3 += c2[k] * hd[k] * hd[k];
            cs += c2[k];
        }
        e0 = wred(e0); e1 = wred(e1); e2 = wred(e2); e3 = wred(e3); cs = wred(cs);
        if (lane == 0) {
            part[204 * 8 + w] = e0; part[205 * 8 + w] = e1;
            part[206 * 8 + w] = e2; part[207 * 8 + w] = e3;
            part[208 * 8 + w] = cs;
        }
    }
    __syncthreads();
    if (tid < NDOT) {
        float s = 0.f;
        #pragma unroll
        for (int k = 0; k < 8; k++) s += part[tid * 8 + k];
        dsm[tid] = s;
    }
    __syncthreads();

    if (tid < 12) {
        int h = tid;
        int pd = h * 12 - (h * (h - 1)) / 2;
        g_tnorm[(b * H_ + h) * S_ + j] = sqrtf(fmaxf(dsm[pd], 0.f));
    }

    if (tid < S_) {
        int i = tid;
        float P[12];
        #pragma unroll
        for (int h = 0; h < 12; h++) P[h] = Psh[i * 13 + h];

        float n1 = 0.f, n3 = 0.f;
        {
            int p = 0;
            #pragma unroll
            for (int h = 0; h < 12; h++) {
                float ph = P[h];
                n1 = fmaf(ph * ph, dsm[p], n1);
                n3 = fmaf(ph * ph, dsm[NPAIR + p], n3);
                p++;
                #pragma unroll
                for (int h2 = h + 1; h2 < 12; h2++) {
                    float pp = 2.f * ph * P[h2];
                    n1 = fmaf(pp, dsm[p], n1);
                    n3 = fmaf(pp, dsm[NPAIR + p], n3);
                    p++;
                }
            }
        }
        float sum_s = 0.f, L = 0.f, sv1 = 0.f, sv2 = 0.f;
        #pragma unroll
        for (int h = 0; h < 12; h++) {
            sum_s = fmaf(P[h], dsm[156 + h], sum_s);
            L     = fmaf(P[h], dsm[168 + h], L);
            sv1   = fmaf(P[h], dsm[180 + h], sv1);
            sv2   = fmaf(P[h], dsm[192 + h], sv2);
        }
        float n2 = n1, Ssum = sum_s, a3 = L, a4 = n3;
        if (i == j) {
            n2   += 2.f * sv1 + dsm[204];
            Ssum += dsm[205];
            a3   += dsm[206];
            a4   += 2.f * sv2 + dsm[207];
        }
        float mean = Ssum * (1.f / D_);
        float is = g_invstd[b * S_ + i];
        int o = (b * S_ + i) * S_ + j;
        o_sn[o]  = sqrtf(fmaxf(n1, 0.f));
        o_rwn[o] = sqrtf(fmaxf(n2, 0.f));
        float pn2 = is * is * (a4 - 2.f * mean * a3 + mean * mean * dsm[208]);
        o_pln[o] = sqrtf(fmaxf(pn2, 0.f));
        g_mean[o] = mean;
    }
}

// ---------------- weighted_norm = probs * tnorm ----------------
__global__ void k_wnorm(const float* __restrict__ probs, float* __restrict__ wn)
{
    int idx = blockIdx.x * blockDim.x + threadIdx.x;
    if (idx < BH_ * SS_) {
        int bh = idx / SS_;
        int j  = idx % S_;
        wn[idx] = probs[idx] * g_tnorm[bh * S_ + j];
    }
}

// ---------------- rowsum partial: grid (7, 6, KS_*B_), 3 heads per split ----------------
__global__ __launch_bounds__(256)
void k_rowsum(const float* __restrict__ P)
{
    const int split = blockIdx.z >> 1;
    const int b     = blockIdx.z & 1;
    const int i0 = blockIdx.x * 32;
    const int d0 = blockIdx.y * 128;
    __shared__ __align__(16) float Ps[32][32];
    __shared__ __align__(16) float Ts[32][128];
    const int tid = threadIdx.x;
    const int tx = tid & 31, ty = tid >> 5;
    ull acc[4][2] = {};

    const int h0 = split * (H_ / KS_), h1 = h0 + (H_ / KS_);
    for (int h = h0; h < h1; h++) {
        const float* Pb = P   + (size_t)(b * H_ + h) * SS_;
        const float* Tb = g_T + (size_t)(b * H_ + h) * S_ * D_;
        for (int j0 = 0; j0 < S_; j0 += 32) {
            for (int idx = tid; idx < 32 * 32; idx += 256) {
                int jj = idx >> 5, ii = idx & 31;
                int gi = i0 + ii, gj = j0 + jj;
                Ps[jj][ii] = (gi < S_ && gj < S_) ? Pb[(size_t)gi * S_ + gj] : 0.f;
            }
            for (int idx = tid; idx < 32 * 128; idx += 256) {
                int jj = idx >> 7, dd = idx & 127;
                int gj = j0 + jj;
                Ts[jj][dd] = (gj < S_) ? Tb[(size_t)gj * D_ + d0 + dd] : 0.f;
            }
            __syncthreads();
            #pragma unroll 8
            for (int jj = 0; jj < 32; jj++) {
                float4 pv = *(const float4*)&Ps[jj][ty * 4];
                float4 tt = *(const float4*)&Ts[jj][tx * 4];
                ull t01 = pack2(tt.x, tt.y), t23 = pack2(tt.z, tt.w);
                ull a0 = pack2(pv.x, pv.x), a1 = pack2(pv.y, pv.y);
                ull a2 = pack2(pv.z, pv.z), a3 = pack2(pv.w, pv.w);
                fma2(acc[0][0], a0, t01); fma2(acc[0][1], a0, t23);
                fma2(acc[1][0], a1, t01); fma2(acc[1][1], a1, t23);
                fma2(acc[2][0], a2, t01); fma2(acc[2][1], a2, t23);
                fma2(acc[3][0], a3, t01); fma2(acc[3][1], a3, t23);
            }
            __syncthreads();
        }
    }
    #pragma unroll
    for (int si = 0; si < 4; si++) {
        int gi = i0 + ty * 4 + si;
        if (gi < S_) {
            float2 lo = unpack2(acc[si][0]), hi = unpack2(acc[si][1]);
            float4 o = make_float4(lo.x, lo.y, hi.x, hi.y);
            *(float4*)&g_rs4[split][((size_t)(b * S_ + gi)) * D_ + d0 + tx * 4] = o;
        }
    }
}

// ---------------- post_ln elementwise: block = (j, b), 192 thr x 4 d, FFMA2 ----------------
__global__ __launch_bounds__(192)
void k_pl(const float* __restrict__ probs, const float* __restrict__ hidden,
          const float* __restrict__ lnw, float* __restrict__ o_pl)
{
    const int j = blockIdx.x, b = blockIdx.y;
    const int tid = threadIdx.x;
    const int d0 = tid * 4;

    ull Tp[12][2];
    #pragma unroll
    for (int h = 0; h < 12; h++) {
        float4 t = *(const float4*)&g_T[((size_t)(b * H_ + h) * S_ + j) * D_ + d0];
        Tp[h][0] = pack2(t.x, t.y);
        Tp[h][1] = pack2(t.z, t.w);
    }
    const float4 hv = *(const float4*)&hidden[((size_t)(b * S_ + j)) * D_ + d0];
    const float4 cv = *(const float4*)&lnw[d0];

    __shared__ __align__(16) float Psh[S_ * 12];
    __shared__ float msh[S_], ish[S_];

    for (int idx = tid; idx < H_ * S_; idx += 192) {
        int i = idx / 12, h = idx % 12;
        Psh[idx] = probs[((size_t)(b * H_ + h) * S_ + i) * S_ + j];
    }
    for (int t = tid; t < S_; t += 192) {
        msh[t] = g_mean[(b * S_ + t) * S_ + j];
        ish[t] = g_invstd[b * S_ + t];
    }
    __syncthreads();

    for (int i = 0; i < S_; i++) {
        const float4* Pp = (const float4*)&Psh[i * 12];
        float4 p0 = Pp[0], p1 = Pp[1], p2 = Pp[2];
        float P[12] = {p0.x, p0.y, p0.z, p0.w, p1.x, p1.y, p1.z, p1.w,
                       p2.x, p2.y, p2.z, p2.w};
        ull acc0 = 0ull, acc1 = 0ull;
        #pragma unroll
        for (int h = 0; h < 12; h++) {
            ull ph = pack2(P[h], P[h]);
            fma2(acc0, ph, Tp[h][0]);
            fma2(acc1, ph, Tp[h][1]);
        }
        float2 sa = unpack2(acc0), sb = unpack2(acc1);
        if (i == j) { sa.x += hv.x; sa.y += hv.y; sb.x += hv.z; sb.y += hv.w; }
        float m = msh[i], is = ish[i];
        float2 oa, ob;
        oa.x = (sa.x - m) * is * cv.x;
        oa.y = (sa.y - m) * is * cv.y;
        ob.x = (sb.x - m) * is * cv.z;
        ob.y = (sb.y - m) * is * cv.w;
        float* dst = &o_pl[((size_t)(b * S_ + i) * S_ + j) * D_ + d0];
        *(float2*)(dst)     = oa;   // o_pl base is 8B-aligned: float2 only
        *(float2*)(dst + 2) = ob;
    }
}

// ---------------- mixing ratios: block = (b, i) ----------------
__global__ __launch_bounds__(768)
void k_mix(const float* __restrict__ probs, const float* __restrict__ hidden,
           const float* __restrict__ lnw,
           float* __restrict__ m1, float* __restrict__ m2, float* __restrict__ m3)
{
    const int blk = blockIdx.x;
    const int b = blk / S_, i = blk % S_;
    const int d = threadIdx.x;
    const int lane = d & 31, w = d >> 5;

    __shared__ float Pd[H_];
    __shared__ float red[5][24];
    __shared__ float bc[8];
    if (d < H_) Pd[d] = probs[((size_t)(b * H_ + d) * S_ + i) * S_ + i];
    __syncthreads();

    float sii = 0.f;
    #pragma unroll
    for (int h = 0; h < H_; h++)
        sii = fmaf(Pd[h], g_T[((size_t)(b * H_ + h) * S_ + i) * D_ + d], sii);

    size_t ridx = ((size_t)(b * S_ + i)) * D_ + d;
    float rs = g_rs4[0][ridx] + g_rs4[1][ridx] + g_rs4[2][ridx] + g_rs4[3][ridx];
    float hd   = hidden[ridx];
    float lw   = lnw[d];
    float mixv = rs - sii;
    float rwii = sii + hd;
    float rsrw = rs + hd;

    float a0 = wred(mixv * mixv);
    float a1 = wred(sii * sii);
    float a2 = wred(rwii * rwii);
    float a3 = wred(rwii);
    float a4 = wred(rsrw);
    if (lane == 0) {
        red[0][w] = a0; red[1][w] = a1; red[2][w] = a2;
        red[3][w] = a3; red[4][w] = a4;
    }
    __syncthreads();
    if (d < 5) {
        float sum = 0.f;
        #pragma unroll
        for (int k = 0; k < 24; k++) sum += red[d][k];
        bc[d] = sum;
    }
    __syncthreads();
    float mn1sq = bc[0], pn1sq = bc[1], pn2sq = bc[2];
    float mean_ii = bc[3] * (1.f / D_);
    float M       = bc[4] * (1.f / D_);
    float is = g_invstd[b * S_ + i];

    float pres3 = (rwii - mean_ii) * is * lw;
    float mix3  = is * lw * (rsrw - M) - pres3;
    float b0 = wred(pres3 * pres3);
    float b1 = wred(mix3 * mix3);
    if (lane == 0) { red[0][w] = b0; red[1][w] = b1; }
    __syncthreads();
    if (d == 0) {
        float B0 = 0.f, B1 = 0.f;
        #pragma unroll
        for (int k = 0; k < 24; k++) { B0 += red[0][k]; B1 += red[1][k]; }
        float mn1 = sqrtf(mn1sq), pn1 = sqrtf(pn1sq), pn2 = sqrtf(pn2sq);
        float pn3 = sqrtf(B0),   mn3 = sqrtf(B1);
        m1[b * S_ + i] = mn1 / (mn1 + pn1);
        m2[b * S_ + i] = mn1 / (mn1 + pn2);
        m3[b * S_ + i] = mn3 / (mn3 + pn3);
    }
}

// ---------------- launch ----------------
extern "C" void kernel_launch(void* const* d_in, const int* in_sizes, int n_in,
                              void* d_out, int out_size)
{
    const float* hidden = (const float*)d_in[0];
    const float* probs  = (const float*)d_in[1];
    const float* value  = (const float*)d_in[2];
    const float* dw     = (const float*)d_in[3];
    const float* lnw    = (const float*)d_in[4];
    const float* preln  = (const float*)d_in[5];

    float* out   = (float*)d_out;
    float* o_wn  = out;
    float* o_sn  = o_wn  + (size_t)BH_ * SS_;
    float* o_rwn = o_sn  + (size_t)B_ * SS_;
    float* o_pln = o_rwn + (size_t)B_ * SS_;
    float* o_pl  = o_pln + (size_t)B_ * SS_;
    float* o_m1  = o_pl  + (size_t)B_ * SS_ * D_;
    float* o_m2  = o_m1  + B_ * S_;
    float* o_m3  = o_m2  + B_ * S_;

    k_invstd<<<B_ * S_, 256>>>(preln);
    k_transformed<<<dim3(7, 6, BH_), 256>>>(value, dw);
    k_scal<<<dim3(S_, B_), 256>>>(probs, hidden, lnw, o_sn, o_rwn, o_pln);
    k_wnorm<<<(BH_ * SS_ + 255) / 256, 256>>>(probs, o_wn);
    k_rowsum<<<dim3(7, 6, KS_ * B_), 256>>>(probs);
    k_pl<<<dim3(S_, B_), 192>>>(probs, hidden, lnw, o_pl);
    k_mix<<<B_ * S_, 768>>>(probs, hidden, lnw, o_m1, o_m2, o_m3);
}

// round 8
// speedup vs baseline: 3.5171x; 1.1931x over previous
#include <cuda_runtime.h>

#define B_   2
#define H_   12
#define S_   197
#define D_   768
#define HD_  64
#define SS_  (S_*S_)
#define BH_  (B_*H_)
#define LN_EPS 1e-12f
#define NPAIR 78
#define NDOT  209
#define KS_   6            // k-split for rowsum (2 heads each)

typedef unsigned long long ull;

// ---------------- scratch (device globals; no allocation) ----------------
__device__ __align__(16) float g_T[BH_*S_*D_];
__device__ __align__(16) float g_tnorm[BH_*S_];
__device__ __align__(16) float g_rs[KS_][B_*S_*D_];
__device__ __align__(16) float g_invstd[B_*S_];
__device__ __align__(16) float g_mean[B_*SS_];
__device__ __align__(16) ull   g_Pp[(size_t)B_*SS_*12];   // P duplicated as f32x2 pairs

__device__ __forceinline__ float wred(float x) {
    #pragma unroll
    for (int o = 16; o; o >>= 1) x += __shfl_xor_sync(0xffffffffu, x, o);
    return x;
}

// ---- packed f32x2 helpers (Blackwell FFMA2/FMUL2 via PTX) ----
__device__ __forceinline__ ull pack2(float lo, float hi) {
    ull r;
    asm("mov.b64 %0, {%1, %2};" : "=l"(r) : "f"(lo), "f"(hi));
    return r;
}
__device__ __forceinline__ void fma2(ull& d, ull a, ull b) {   // d = a*b + d
    asm("fma.rn.f32x2 %0, %1, %2, %0;" : "+l"(d) : "l"(a), "l"(b));
}
__device__ __forceinline__ ull mul2(ull a, ull b) {
    ull r;
    asm("mul.rn.f32x2 %0, %1, %2;" : "=l"(r) : "l"(a), "l"(b));
    return r;
}
__device__ __forceinline__ float2 unpack2(ull v) {
    float2 f;
    asm("mov.b64 {%0, %1}, %2;" : "=f"(f.x), "=f"(f.y) : "l"(v));
    return f;
}

// ---------------- transformed GEMM + fused invstd ----------------
// grid (7, 6, BH_+1): z < BH_ -> transformed tile; z == BH_ -> invstd rows
__global__ __launch_bounds__(256)
void k_tri(const float* __restrict__ V, const float* __restrict__ W,
           const float* __restrict__ preln)
{
    __shared__ __align__(16) float Vs[64][32];
    __shared__ __align__(16) float Ws[64][128];
    const int tid = threadIdx.x;

    if (blockIdx.z == BH_) {
        // ---- invstd: 42 blocks cover 394 rows ----
        __shared__ float sh0[8], sh1[8];
        int q = blockIdx.x * 6 + blockIdx.y;
        for (int row = q; row < B_ * S_; row += 42) {
            const float* x = preln + (size_t)row * D_;
            float s = 0.f, s2 = 0.f;
            for (int d = tid; d < D_; d += 256) {
                float v = x[d];
                s += v; s2 += v * v;
            }
            s = wred(s); s2 = wred(s2);
            if ((tid & 31) == 0) { sh0[tid >> 5] = s; sh1[tid >> 5] = s2; }
            __syncthreads();
            if (tid == 0) {
                float S = 0.f, S2 = 0.f;
                #pragma unroll
                for (int w = 0; w < 8; w++) { S += sh0[w]; S2 += sh1[w]; }
                float mean = S * (1.f / D_);
                float var  = S2 * (1.f / D_) - mean * mean;
                g_invstd[row] = rsqrtf(var + LN_EPS);
            }
            __syncthreads();
        }
        return;
    }

    const int bh = blockIdx.z;
    const int h  = bh % H_;
    const int s0 = blockIdx.x * 32;
    const int d0 = blockIdx.y * 128;

    for (int idx = tid; idx < 64 * 32; idx += 256) {
        int v = idx >> 5, s = idx & 31;
        int gs = s0 + s;
        Vs[v][s] = (gs < S_) ? V[((size_t)bh * S_ + gs) * HD_ + v] : 0.f;
    }
    for (int idx = tid; idx < 64 * 128; idx += 256) {
        int v = idx >> 7, dd = idx & 127;
        Ws[v][dd] = W[(size_t)(d0 + dd) * D_ + h * HD_ + v];
    }
    __syncthreads();

    const int tx = tid & 31;
    const int ty = tid >> 5;
    ull acc[4][2] = {};
    #pragma unroll
    for (int v = 0; v < 64; v++) {
        float4 vv = *(const float4*)&Vs[v][ty * 4];
        float4 ww = *(const float4*)&Ws[v][tx * 4];
        ull t01 = pack2(ww.x, ww.y), t23 = pack2(ww.z, ww.w);
        ull a0 = pack2(vv.x, vv.x), a1 = pack2(vv.y, vv.y);
        ull a2 = pack2(vv.z, vv.z), a3 = pack2(vv.w, vv.w);
        fma2(acc[0][0], a0, t01); fma2(acc[0][1], a0, t23);
        fma2(acc[1][0], a1, t01); fma2(acc[1][1], a1, t23);
        fma2(acc[2][0], a2, t01); fma2(acc[2][1], a2, t23);
        fma2(acc[3][0], a3, t01); fma2(acc[3][1], a3, t23);
    }
    #pragma unroll
    for (int si = 0; si < 4; si++) {
        int s = s0 + ty * 4 + si;
        if (s < S_) {
            float2 lo = unpack2(acc[si][0]), hi = unpack2(acc[si][1]);
            float4 o = make_float4(lo.x, lo.y, hi.x, hi.y);
            *(float4*)&g_T[((size_t)bh * S_ + s) * D_ + d0 + tx * 4] = o;
        }
    }
}

// ---------------- scalar kernel: Gram matrices + all per-(i,j) scalars ----------------
__global__ __launch_bounds__(256)
void k_scal(const float* __restrict__ probs, const float* __restrict__ hidden,
            const float* __restrict__ lnw,
            float* __restrict__ o_sn, float* __restrict__ o_rwn,
            float* __restrict__ o_pln)
{
    const int j = blockIdx.x, b = blockIdx.y;
    const int tid = threadIdx.x;
    const int lane = tid & 31, w = tid >> 5;

    __shared__ float part[NDOT * 8];
    __shared__ float dsm[NDOT];
    __shared__ float Psh[S_ * 13];

    float T[12][3], hd[3], c2[3];
    #pragma unroll
    for (int h = 0; h < 12; h++) {
        const float* tp = g_T + ((size_t)(b * H_ + h) * S_ + j) * D_ + tid;
        #pragma unroll
        for (int k = 0; k < 3; k++) T[h][k] = tp[k * 256];
    }
    {
        const float* hp = hidden + ((size_t)(b * S_ + j)) * D_ + tid;
        const float* cp = lnw + tid;
        #pragma unroll
        for (int k = 0; k < 3; k++) {
            hd[k] = hp[k * 256];
            float c = cp[k * 256];
            c2[k] = c * c;
        }
    }

    // gather P; also emit duplicated-pair layout for k_pl
    const size_t pbase = ((size_t)(b * S_ + j)) * S_ * 12;
    for (int idx = tid; idx < H_ * S_; idx += 256) {
        int i = idx / 12, h = idx % 12;
        float v = probs[((size_t)(b * H_ + h) * S_ + i) * S_ + j];
        Psh[i * 13 + h] = v;
        g_Pp[pbase + idx] = pack2(v, v);
    }

    {
        int p = 0;
        #pragma unroll
        for (int h = 0; h < 12; h++) {
            #pragma unroll
            for (int h2 = h; h2 < 12; h2++) {
                float q0 = T[h][0] * T[h2][0];
                float q1 = T[h][1] * T[h2][1];
                float q2 = T[h][2] * T[h2][2];
                float g1 = q0 + q1 + q2;
                float g2 = c2[0] * q0 + c2[1] * q1 + c2[2] * q2;
                g1 = wred(g1); g2 = wred(g2);
                if (lane == 0) {
                    part[p * 8 + w]           = g1;
                    part[(NPAIR + p) * 8 + w] = g2;
                }
                p++;
            }
        }
    }
    #pragma unroll
    for (int h = 0; h < 12; h++) {
        float u1 = T[h][0] + T[h][1] + T[h][2];
        float u2 = c2[0] * T[h][0] + c2[1] * T[h][1] + c2[2] * T[h][2];
        float q0 = T[h][0] * hd[0], q1 = T[h][1] * hd[1], q2 = T[h][2] * hd[2];
        float v1 = q0 + q1 + q2;
        float v2 = c2[0] * q0 + c2[1] * q1 + c2[2] * q2;
        u1 = wred(u1); u2 = wred(u2); v1 = wred(v1); v2 = wred(v2);
        if (lane == 0) {
            part[(156 + h) * 8 + w] = u1;
            part[(168 + h) * 8 + w] = u2;
            part[(180 + h) * 8 + w] = v1;
            part[(192 + h) * 8 + w] = v2;
        }
    }
    {
        float e0 = 0.f, e1 = 0.f, e2 = 0.f, e3 = 0.f, cs = 0.f;
        #pragma unroll
        for (int k = 0; k < 3; k++) {
            e0 += hd[k] * hd[k];
            e1 += hd[k];
            e2 += c2[k] * hd[k];
            e3 += c2[k] * hd[k] * hd[k];
            cs += c2[k];
        }
        e0 = wred(e0); e1 = wred(e1); e2 = wred(e2); e3 = wred(e3); cs = wred(cs);
        if (lane == 0) {
            part[204 * 8 + w] = e0; part[205 * 8 + w] = e1;
            part[206 * 8 + w] = e2; part[207 * 8 + w] = e3;
            part[208 * 8 + w] = cs;
        }
    }
    __syncthreads();
    if (tid < NDOT) {
        float s = 0.f;
        #pragma unroll
        for (int k = 0; k < 8; k++) s += part[tid * 8 + k];
        dsm[tid] = s;
    }
    __syncthreads();

    if (tid < 12) {
        int h = tid;
        int pd = h * 12 - (h * (h - 1)) / 2;
        g_tnorm[(b * H_ + h) * S_ + j] = sqrtf(fmaxf(dsm[pd], 0.f));
    }

    if (tid < S_) {
        int i = tid;
        float P[12];
        #pragma unroll
        for (int h = 0; h < 12; h++) P[h] = Psh[i * 13 + h];

        float n1 = 0.f, n3 = 0.f;
        {
            int p = 0;
            #pragma unroll
            for (int h = 0; h < 12; h++) {
                float ph = P[h];
                n1 = fmaf(ph * ph, dsm[p], n1);
                n3 = fmaf(ph * ph, dsm[NPAIR + p], n3);
                p++;
                #pragma unroll
                for (int h2 = h + 1; h2 < 12; h2++) {
                    float pp = 2.f * ph * P[h2];
                    n1 = fmaf(pp, dsm[p], n1);
                    n3 = fmaf(pp, dsm[NPAIR + p], n3);
                    p++;
                }
            }
        }
        float sum_s = 0.f, L = 0.f, sv1 = 0.f, sv2 = 0.f;
        #pragma unroll
        for (int h = 0; h < 12; h++) {
            sum_s = fmaf(P[h], dsm[156 + h], sum_s);
            L     = fmaf(P[h], dsm[168 + h], L);
            sv1   = fmaf(P[h], dsm[180 + h], sv1);
            sv2   = fmaf(P[h], dsm[192 + h], sv2);
        }
        float n2 = n1, Ssum = sum_s, a3 = L, a4 = n3;
        if (i == j) {
            n2   += 2.f * sv1 + dsm[204];
            Ssum += dsm[205];
            a3   += dsm[206];
            a4   += 2.f * sv2 + dsm[207];
        }
        float mean = Ssum * (1.f / D_);
        float is = g_invstd[b * S_ + i];
        int o = (b * S_ + i) * S_ + j;
        o_sn[o]  = sqrtf(fmaxf(n1, 0.f));
        o_rwn[o] = sqrtf(fmaxf(n2, 0.f));
        float pn2 = is * is * (a4 - 2.f * mean * a3 + mean * mean * dsm[208]);
        o_pln[o] = sqrtf(fmaxf(pn2, 0.f));
        g_mean[o] = mean;
    }
}

// ---------------- rowsum partial: grid (7, 6, KS_*B_), 2 heads per split ----------------
__global__ __launch_bounds__(256)
void k_rowsum(const float* __restrict__ P)
{
    const int split = blockIdx.z >> 1;
    const int b     = blockIdx.z & 1;
    const int i0 = blockIdx.x * 32;
    const int d0 = blockIdx.y * 128;
    __shared__ __align__(16) float Ps[32][32];
    __shared__ __align__(16) float Ts[32][128];
    const int tid = threadIdx.x;
    const int tx = tid & 31, ty = tid >> 5;
    ull acc[4][2] = {};

    const int h0 = split * (H_ / KS_), h1 = h0 + (H_ / KS_);
    for (int h = h0; h < h1; h++) {
        const float* Pb = P   + (size_t)(b * H_ + h) * SS_;
        const float* Tb = g_T + (size_t)(b * H_ + h) * S_ * D_;
        for (int j0 = 0; j0 < S_; j0 += 32) {
            for (int idx = tid; idx < 32 * 32; idx += 256) {
                int jj = idx >> 5, ii = idx & 31;
                int gi = i0 + ii, gj = j0 + jj;
                Ps[jj][ii] = (gi < S_ && gj < S_) ? Pb[(size_t)gi * S_ + gj] : 0.f;
            }
            for (int idx = tid; idx < 32 * 128; idx += 256) {
                int jj = idx >> 7, dd = idx & 127;
                int gj = j0 + jj;
                Ts[jj][dd] = (gj < S_) ? Tb[(size_t)gj * D_ + d0 + dd] : 0.f;
            }
            __syncthreads();
            #pragma unroll 8
            for (int jj = 0; jj < 32; jj++) {
                float4 pv = *(const float4*)&Ps[jj][ty * 4];
                float4 tt = *(const float4*)&Ts[jj][tx * 4];
                ull t01 = pack2(tt.x, tt.y), t23 = pack2(tt.z, tt.w);
                ull a0 = pack2(pv.x, pv.x), a1 = pack2(pv.y, pv.y);
                ull a2 = pack2(pv.z, pv.z), a3 = pack2(pv.w, pv.w);
                fma2(acc[0][0], a0, t01); fma2(acc[0][1], a0, t23);
                fma2(acc[1][0], a1, t01); fma2(acc[1][1], a1, t23);
                fma2(acc[2][0], a2, t01); fma2(acc[2][1], a2, t23);
                fma2(acc[3][0], a3, t01); fma2(acc[3][1], a3, t23);
            }
            __syncthreads();
        }
    }
    #pragma unroll
    for (int si = 0; si < 4; si++) {
        int gi = i0 + ty * 4 + si;
        if (gi < S_) {
            float2 lo = unpack2(acc[si][0]), hi = unpack2(acc[si][1]);
            float4 o = make_float4(lo.x, lo.y, hi.x, hi.y);
            *(float4*)&g_rs[split][((size_t)(b * S_ + gi)) * D_ + d0 + tx * 4] = o;
        }
    }
}

// ---------------- post_ln elementwise: block = (j, b, half), 192 thr x 4 d ----------------
__global__ __launch_bounds__(192)
void k_pl(const float* __restrict__ hidden, const float* __restrict__ lnw,
          float* __restrict__ o_pl)
{
    const int j = blockIdx.x, b = blockIdx.y, half = blockIdx.z;
    const int tid = threadIdx.x;
    const int d0 = tid * 4;

    ull Tp[12][2];
    #pragma unroll
    for (int h = 0; h < 12; h++) {
        float4 t = *(const float4*)&g_T[((size_t)(b * H_ + h) * S_ + j) * D_ + d0];
        Tp[h][0] = pack2(t.x, t.y);
        Tp[h][1] = pack2(t.z, t.w);
    }
    const float4 hv = *(const float4*)&hidden[((size_t)(b * S_ + j)) * D_ + d0];
    const float4 cvf = *(const float4*)&lnw[d0];
    const ull cv01 = pack2(cvf.x, cvf.y), cv23 = pack2(cvf.z, cvf.w);

    __shared__ __align__(16) ull Pp[S_ * 12];   // 18.9 KB, prepacked pairs
    __shared__ float msh[S_], ish[S_];

    const ull* src = g_Pp + ((size_t)(b * S_ + j)) * S_ * 12;
    for (int idx = tid; idx < (S_ * 12) / 2; idx += 192)
        *(ulonglong2*)&Pp[idx * 2] = *(const ulonglong2*)&src[idx * 2];
    for (int t = tid; t < S_; t += 192) {
        msh[t] = g_mean[(b * S_ + t) * S_ + j];
        ish[t] = g_invstd[b * S_ + t];
    }
    __syncthreads();

    const int i0 = half ? 99 : 0;
    const int i1 = half ? S_ : 99;
    float* dst = &o_pl[((size_t)(b * S_ + i0) * S_ + j) * D_ + d0];
    for (int i = i0; i < i1; i++) {
        ull P[12];
        #pragma unroll
        for (int k = 0; k < 6; k++)
            *(ulonglong2*)&P[k * 2] = *(const ulonglong2*)&Pp[i * 12 + k * 2];
        ull acc0 = 0ull, acc1 = 0ull;
        #pragma unroll
        for (int h = 0; h < 12; h++) {
            fma2(acc0, P[h], Tp[h][0]);
            fma2(acc1, P[h], Tp[h][1]);
        }
        float2 sa = unpack2(acc0), sb = unpack2(acc1);
        if (i == j) { sa.x += hv.x; sa.y += hv.y; sb.x += hv.z; sb.y += hv.w; }
        float m = msh[i], is = ish[i];
        float pre = -m * is;
        ull is2  = pack2(is, is);
        ull o01  = pack2(pre, pre), o23 = o01;
        fma2(o01, pack2(sa.x, sa.y), is2);
        fma2(o23, pack2(sb.x, sb.y), is2);
        o01 = mul2(o01, cv01);
        o23 = mul2(o23, cv23);
        __stcs((float2*)dst,       unpack2(o01));
        __stcs((float2*)(dst + 2), unpack2(o23));
        dst += (size_t)S_ * D_;
    }
}

// ---------------- mixing ratios + weighted_norm ----------------
__global__ __launch_bounds__(768)
void k_mixwn(const float* __restrict__ probs, const float* __restrict__ hidden,
             const float* __restrict__ lnw,
             float* __restrict__ m1, float* __restrict__ m2, float* __restrict__ m3,
             float* __restrict__ wn)
{
    const int blk = blockIdx.x;
    const int b = blk / S_, i = blk % S_;
    const int d = threadIdx.x;
    const int lane = d & 31, w = d >> 5;

    __shared__ float Pd[H_];
    __shared__ float red[5][24];
    __shared__ float bc[8];
    if (d < H_) Pd[d] = probs[((size_t)(b * H_ + d) * S_ + i) * S_ + i];
    __syncthreads();

    float sii = 0.f;
    #pragma unroll
    for (int h = 0; h < H_; h++)
        sii = fmaf(Pd[h], g_T[((size_t)(b * H_ + h) * S_ + i) * D_ + d], sii);

    size_t ridx = ((size_t)(b * S_ + i)) * D_ + d;
    float rs = 0.f;
    #pragma unroll
    for (int k = 0; k < KS_; k++) rs += g_rs[k][ridx];
    float hd   = hidden[ridx];
    float lw   = lnw[d];
    float mixv = rs - sii;
    float rwii = sii + hd;
    float rsrw = rs + hd;

    float a0 = wred(mixv * mixv);
    float a1 = wred(sii * sii);
    float a2 = wred(rwii * rwii);
    float a3 = wred(rwii);
    float a4 = wred(rsrw);
    if (lane == 0) {
        red[0][w] = a0; red[1][w] = a1; red[2][w] = a2;
        red[3][w] = a3; red[4][w] = a4;
    }
    __syncthreads();
    if (d < 5) {
        float sum = 0.f;
        #pragma unroll
        for (int k = 0; k < 24; k++) sum += red[d][k];
        bc[d] = sum;
    }
    __syncthreads();
    float mn1sq = bc[0], pn1sq = bc[1], pn2sq = bc[2];
    float mean_ii = bc[3] * (1.f / D_);
    float M       = bc[4] * (1.f / D_);
    float is = g_invstd[b * S_ + i];

    float pres3 = (rwii - mean_ii) * is * lw;
    float mix3  = is * lw * (rsrw - M) - pres3;
    float b0 = wred(pres3 * pres3);
    float b1 = wred(mix3 * mix3);
    if (lane == 0) { red[0][w] = b0; red[1][w] = b1; }
    __syncthreads();
    if (d == 0) {
        float B0 = 0.f, B1 = 0.f;
        #pragma unroll
        for (int k = 0; k < 24; k++) { B0 += red[0][k]; B1 += red[1][k]; }
        float mn1 = sqrtf(mn1sq), pn1 = sqrtf(pn1sq), pn2 = sqrtf(pn2sq);
        float pn3 = sqrtf(B0),   mn3 = sqrtf(B1);
        m1[b * S_ + i] = mn1 / (mn1 + pn1);
        m2[b * S_ + i] = mn1 / (mn1 + pn2);
        m3[b * S_ + i] = mn3 / (mn3 + pn3);
    }

    // fused weighted_norm: grid-stride over (B,H,S,S)
    for (int idx = blk * 768 + d; idx < BH_ * SS_; idx += B_ * S_ * 768) {
        int bh = idx / SS_;
        int jj = idx % S_;
        __stcs(&wn[idx], probs[idx] * g_tnorm[bh * S_ + jj]);
    }
}

// ---------------- launch ----------------
extern "C" void kernel_launch(void* const* d_in, const int* in_sizes, int n_in,
                              void* d_out, int out_size)
{
    const float* hidden = (const float*)d_in[0];
    const float* probs  = (const float*)d_in[1];
    const float* value  = (const float*)d_in[2];
    const float* dw     = (const float*)d_in[3];
    const float* lnw    = (const float*)d_in[4];
    const float* preln  = (const float*)d_in[5];

    float* out   = (float*)d_out;
    float* o_wn  = out;
    float* o_sn  = o_wn  + (size_t)BH_ * SS_;
    float* o_rwn = o_sn  + (size_t)B_ * SS_;
    float* o_pln = o_rwn + (size_t)B_ * SS_;
    float* o_pl  = o_pln + (size_t)B_ * SS_;
    float* o_m1  = o_pl  + (size_t)B_ * SS_ * D_;
    float* o_m2  = o_m1  + B_ * S_;
    float* o_m3  = o_m2  + B_ * S_;

    k_tri<<<dim3(7, 6, BH_ + 1), 256>>>(value, dw, preln);
    k_scal<<<dim3(S_, B_), 256>>>(probs, hidden, lnw, o_sn, o_rwn, o_pln);
    k_rowsum<<<dim3(7, 6, KS_ * B_), 256>>>(probs);
    k_mixwn<<<B_ * S_, 768>>>(probs, hidden, lnw, o_m1, o_m2, o_m3, o_wn);
    k_pl<<<dim3(S_, B_, 2), 192>>>(hidden, lnw, o_pl);
}

// round 9
// speedup vs baseline: 4.0621x; 1.1550x over previous
#include <cuda_runtime.h>

#define B_   2
#define H_   12
#define S_   197
#define D_   768
#define HD_  64
#define SS_  (S_*S_)
#define BH_  (B_*H_)
#define LN_EPS 1e-12f
#define NPAIR 78
#define NDOT  209
#define KS_   6            // k-split for rowsum (2 heads each)

typedef unsigned long long ull;

// ---------------- scratch (device globals; no allocation) ----------------
__device__ __align__(16) float g_T[BH_*S_*D_];
__device__ __align__(16) float g_tnorm[BH_*S_];
__device__ __align__(16) float g_rs[KS_][B_*S_*D_];
__device__ __align__(16) float g_invstd[B_*S_];
__device__ __align__(16) float g_mean[B_*SS_];
__device__ __align__(16) ull   g_Pp[(size_t)B_*SS_*12];   // P duplicated as f32x2 pairs

__device__ __forceinline__ float wred(float x) {
    #pragma unroll
    for (int o = 16; o; o >>= 1) x += __shfl_xor_sync(0xffffffffu, x, o);
    return x;
}

// ---- packed f32x2 helpers ----
__device__ __forceinline__ ull pack2(float lo, float hi) {
    ull r;
    asm("mov.b64 %0, {%1, %2};" : "=l"(r) : "f"(lo), "f"(hi));
    return r;
}
__device__ __forceinline__ void fma2(ull& d, ull a, ull b) {   // d = a*b + d
    asm("fma.rn.f32x2 %0, %1, %2, %0;" : "+l"(d) : "l"(a), "l"(b));
}
__device__ __forceinline__ ull mul2(ull a, ull b) {
    ull r;
    asm("mul.rn.f32x2 %0, %1, %2;" : "=l"(r) : "l"(a), "l"(b));
    return r;
}
__device__ __forceinline__ ull add2(ull a, ull b) {
    ull r;
    asm("add.rn.f32x2 %0, %1, %2;" : "=l"(r) : "l"(a), "l"(b));
    return r;
}
__device__ __forceinline__ float2 unpack2(ull v) {
    float2 f;
    asm("mov.b64 {%0, %1}, %2;" : "=f"(f.x), "=f"(f.y) : "l"(v));
    return f;
}

// ---------------- transformed GEMM + fused invstd ----------------
__global__ __launch_bounds__(256)
void k_tri(const float* __restrict__ V, const float* __restrict__ W,
           const float* __restrict__ preln)
{
    __shared__ __align__(16) float Vs[64][32];
    __shared__ __align__(16) float Ws[64][128];
    const int tid = threadIdx.x;

    if (blockIdx.z == BH_) {
        __shared__ float sh0[8], sh1[8];
        int q = blockIdx.x * 6 + blockIdx.y;
        for (int row = q; row < B_ * S_; row += 42) {
            const float* x = preln + (size_t)row * D_;
            float s = 0.f, s2 = 0.f;
            for (int d = tid; d < D_; d += 256) {
                float v = x[d];
                s += v; s2 += v * v;
            }
            s = wred(s); s2 = wred(s2);
            if ((tid & 31) == 0) { sh0[tid >> 5] = s; sh1[tid >> 5] = s2; }
            __syncthreads();
            if (tid == 0) {
                float S = 0.f, S2 = 0.f;
                #pragma unroll
                for (int w = 0; w < 8; w++) { S += sh0[w]; S2 += sh1[w]; }
                float mean = S * (1.f / D_);
                float var  = S2 * (1.f / D_) - mean * mean;
                g_invstd[row] = rsqrtf(var + LN_EPS);
            }
            __syncthreads();
        }
        return;
    }

    const int bh = blockIdx.z;
    const int h  = bh % H_;
    const int s0 = blockIdx.x * 32;
    const int d0 = blockIdx.y * 128;

    for (int idx = tid; idx < 64 * 32; idx += 256) {
        int v = idx >> 5, s = idx & 31;
        int gs = s0 + s;
        Vs[v][s] = (gs < S_) ? V[((size_t)bh * S_ + gs) * HD_ + v] : 0.f;
    }
    for (int idx = tid; idx < 64 * 128; idx += 256) {
        int v = idx >> 7, dd = idx & 127;
        Ws[v][dd] = W[(size_t)(d0 + dd) * D_ + h * HD_ + v];
    }
    __syncthreads();

    const int tx = tid & 31;
    const int ty = tid >> 5;
    ull acc[4][2] = {};
    #pragma unroll
    for (int v = 0; v < 64; v++) {
        float4 vv = *(const float4*)&Vs[v][ty * 4];
        float4 ww = *(const float4*)&Ws[v][tx * 4];
        ull t01 = pack2(ww.x, ww.y), t23 = pack2(ww.z, ww.w);
        ull a0 = pack2(vv.x, vv.x), a1 = pack2(vv.y, vv.y);
        ull a2 = pack2(vv.z, vv.z), a3 = pack2(vv.w, vv.w);
        fma2(acc[0][0], a0, t01); fma2(acc[0][1], a0, t23);
        fma2(acc[1][0], a1, t01); fma2(acc[1][1], a1, t23);
        fma2(acc[2][0], a2, t01); fma2(acc[2][1], a2, t23);
        fma2(acc[3][0], a3, t01); fma2(acc[3][1], a3, t23);
    }
    #pragma unroll
    for (int si = 0; si < 4; si++) {
        int s = s0 + ty * 4 + si;
        if (s < S_) {
            float2 lo = unpack2(acc[si][0]), hi = unpack2(acc[si][1]);
            float4 o = make_float4(lo.x, lo.y, hi.x, hi.y);
            *(float4*)&g_T[((size_t)bh * S_ + s) * D_ + d0 + tx * 4] = o;
        }
    }
}

// ---------------- scalar kernel: Gram matrices + all per-(i,j) scalars ----------------
__global__ __launch_bounds__(256)
void k_scal(const float* __restrict__ probs, const float* __restrict__ hidden,
            const float* __restrict__ lnw,
            float* __restrict__ o_sn, float* __restrict__ o_rwn,
            float* __restrict__ o_pln)
{
    const int j = blockIdx.x, b = blockIdx.y;
    const int tid = threadIdx.x;
    const int lane = tid & 31, w = tid >> 5;

    __shared__ float part[NDOT * 8];
    __shared__ float dsm[NDOT];
    __shared__ float Psh[S_ * 13];

    float T[12][3], hd[3], c2[3];
    #pragma unroll
    for (int h = 0; h < 12; h++) {
        const float* tp = g_T + ((size_t)(b * H_ + h) * S_ + j) * D_ + tid;
        #pragma unroll
        for (int k = 0; k < 3; k++) T[h][k] = tp[k * 256];
    }
    {
        const float* hp = hidden + ((size_t)(b * S_ + j)) * D_ + tid;
        const float* cp = lnw + tid;
        #pragma unroll
        for (int k = 0; k < 3; k++) {
            hd[k] = hp[k * 256];
            float c = cp[k * 256];
            c2[k] = c * c;
        }
    }

    const size_t pbase = ((size_t)(b * S_ + j)) * S_ * 12;
    for (int idx = tid; idx < H_ * S_; idx += 256) {
        int i = idx / 12, h = idx % 12;
        float v = probs[((size_t)(b * H_ + h) * S_ + i) * S_ + j];
        Psh[i * 13 + h] = v;
        g_Pp[pbase + idx] = pack2(v, v);
    }

    {
        int p = 0;
        #pragma unroll
        for (int h = 0; h < 12; h++) {
            #pragma unroll
            for (int h2 = h; h2 < 12; h2++) {
                float q0 = T[h][0] * T[h2][0];
                float q1 = T[h][1] * T[h2][1];
                float q2 = T[h][2] * T[h2][2];
                float g1 = q0 + q1 + q2;
                float g2 = c2[0] * q0 + c2[1] * q1 + c2[2] * q2;
                g1 = wred(g1); g2 = wred(g2);
                if (lane == 0) {
                    part[p * 8 + w]           = g1;
                    part[(NPAIR + p) * 8 + w] = g2;
                }
                p++;
            }
        }
    }
    #pragma unroll
    for (int h = 0; h < 12; h++) {
        float u1 = T[h][0] + T[h][1] + T[h][2];
        float u2 = c2[0] * T[h][0] + c2[1] * T[h][1] + c2[2] * T[h][2];
        float q0 = T[h][0] * hd[0], q1 = T[h][1] * hd[1], q2 = T[h][2] * hd[2];
        float v1 = q0 + q1 + q2;
        float v2 = c2[0] * q0 + c2[1] * q1 + c2[2] * q2;
        u1 = wred(u1); u2 = wred(u2); v1 = wred(v1); v2 = wred(v2);
        if (lane == 0) {
            part[(156 + h) * 8 + w] = u1;
            part[(168 + h) * 8 + w] = u2;
            part[(180 + h) * 8 + w] = v1;
            part[(192 + h) * 8 + w] = v2;
        }
    }
    {
        float e0 = 0.f, e1 = 0.f, e2 = 0.f, e3 = 0.f, cs = 0.f;
        #pragma unroll
        for (int k = 0; k < 3; k++) {
            e0 += hd[k] * hd[k];
            e1 += hd[k];
            e2 += c2[k] * hd[k];
            e3 += c2[k] * hd[k] * hd[k];
            cs += c2[k];
        }
        e0 = wred(e0); e1 = wred(e1); e2 = wred(e2); e3 = wred(e3); cs = wred(cs);
        if (lane == 0) {
            part[204 * 8 + w] = e0; part[205 * 8 + w] = e1;
            part[206 * 8 + w] = e2; part[207 * 8 + w] = e3;
            part[208 * 8 + w] = cs;
        }
    }
    __syncthreads();
    if (tid < NDOT) {
        float s = 0.f;
        #pragma unroll
        for (int k = 0; k < 8; k++) s += part[tid * 8 + k];
        dsm[tid] = s;
    }
    __syncthreads();

    if (tid < 12) {
        int h = tid;
        int pd = h * 12 - (h * (h - 1)) / 2;
        g_tnorm[(b * H_ + h) * S_ + j] = sqrtf(fmaxf(dsm[pd], 0.f));
    }

    if (tid < S_) {
        int i = tid;
        float P[12];
        #pragma unroll
        for (int h = 0; h < 12; h++) P[h] = Psh[i * 13 + h];

        float n1 = 0.f, n3 = 0.f;
        {
            int p = 0;
            #pragma unroll
            for (int h = 0; h < 12; h++) {
                float ph = P[h];
                n1 = fmaf(ph * ph, dsm[p], n1);
                n3 = fmaf(ph * ph, dsm[NPAIR + p], n3);
                p++;
                #pragma unroll
                for (int h2 = h + 1; h2 < 12; h2++) {
                    float pp = 2.f * ph * P[h2];
                    n1 = fmaf(pp, dsm[p], n1);
                    n3 = fmaf(pp, dsm[NPAIR + p], n3);
                    p++;
                }
            }
        }
        float sum_s = 0.f, L = 0.f, sv1 = 0.f, sv2 = 0.f;
        #pragma unroll
        for (int h = 0; h < 12; h++) {
            sum_s = fmaf(P[h], dsm[156 + h], sum_s);
            L     = fmaf(P[h], dsm[168 + h], L);
            sv1   = fmaf(P[h], dsm[180 + h], sv1);
            sv2   = fmaf(P[h], dsm[192 + h], sv2);
        }
        float n2 = n1, Ssum = sum_s, a3 = L, a4 = n3;
        if (i == j) {
            n2   += 2.f * sv1 + dsm[204];
            Ssum += dsm[205];
            a3   += dsm[206];
            a4   += 2.f * sv2 + dsm[207];
        }
        float mean = Ssum * (1.f / D_);
        float is = g_invstd[b * S_ + i];
        int o = (b * S_ + i) * S_ + j;
        o_sn[o]  = sqrtf(fmaxf(n1, 0.f));
        o_rwn[o] = sqrtf(fmaxf(n2, 0.f));
        float pn2 = is * is * (a4 - 2.f * mean * a3 + mean * mean * dsm[208]);
        o_pln[o] = sqrtf(fmaxf(pn2, 0.f));
        g_mean[o] = mean;
    }
}

// ---------------- rowsum partial: grid (7, 6, KS_*B_) ----------------
__global__ __launch_bounds__(256)
void k_rowsum(const float* __restrict__ P)
{
    const int split = blockIdx.z >> 1;
    const int b     = blockIdx.z & 1;
    const int i0 = blockIdx.x * 32;
    const int d0 = blockIdx.y * 128;
    __shared__ __align__(16) float Ps[32][32];
    __shared__ __align__(16) float Ts[32][128];
    const int tid = threadIdx.x;
    const int tx = tid & 31, ty = tid >> 5;
    ull acc[4][2] = {};

    const int h0 = split * (H_ / KS_), h1 = h0 + (H_ / KS_);
    for (int h = h0; h < h1; h++) {
        const float* Pb = P   + (size_t)(b * H_ + h) * SS_;
        const float* Tb = g_T + (size_t)(b * H_ + h) * S_ * D_;
        for (int j0 = 0; j0 < S_; j0 += 32) {
            for (int idx = tid; idx < 32 * 32; idx += 256) {
                int jj = idx >> 5, ii = idx & 31;
                int gi = i0 + ii, gj = j0 + jj;
                Ps[jj][ii] = (gi < S_ && gj < S_) ? Pb[(size_t)gi * S_ + gj] : 0.f;
            }
            for (int idx = tid; idx < 32 * 128; idx += 256) {
                int jj = idx >> 7, dd = idx & 127;
                int gj = j0 + jj;
                Ts[jj][dd] = (gj < S_) ? Tb[(size_t)gj * D_ + d0 + dd] : 0.f;
            }
            __syncthreads();
            #pragma unroll 8
            for (int jj = 0; jj < 32; jj++) {
                float4 pv = *(const float4*)&Ps[jj][ty * 4];
                float4 tt = *(const float4*)&Ts[jj][tx * 4];
                ull t01 = pack2(tt.x, tt.y), t23 = pack2(tt.z, tt.w);
                ull a0 = pack2(pv.x, pv.x), a1 = pack2(pv.y, pv.y);
                ull a2 = pack2(pv.z, pv.z), a3 = pack2(pv.w, pv.w);
                fma2(acc[0][0], a0, t01); fma2(acc[0][1], a0, t23);
                fma2(acc[1][0], a1, t01); fma2(acc[1][1], a1, t23);
                fma2(acc[2][0], a2, t01); fma2(acc[2][1], a2, t23);
                fma2(acc[3][0], a3, t01); fma2(acc[3][1], a3, t23);
            }
            __syncthreads();
        }
    }
    #pragma unroll
    for (int si = 0; si < 4; si++) {
        int gi = i0 + ty * 4 + si;
        if (gi < S_) {
            float2 lo = unpack2(acc[si][0]), hi = unpack2(acc[si][1]);
            float4 o = make_float4(lo.x, lo.y, hi.x, hi.y);
            *(float4*)&g_rs[split][((size_t)(b * S_ + gi)) * D_ + d0 + tx * 4] = o;
        }
    }
}

// ---------------- post_ln elementwise: block = (j, b, half), 192 thr x 4 d ----------------
__global__ __launch_bounds__(192)
void k_pl(const float* __restrict__ hidden, const float* __restrict__ lnw,
          float* __restrict__ o_pl)
{
    const int j = blockIdx.x, b = blockIdx.y, half = blockIdx.z;
    const int tid = threadIdx.x;
    const int d0 = tid * 4;

    const float4 cvf = *(const float4*)&lnw[d0];
    // fold lnw into T once per block
    ull Tc[12][2];
    #pragma unroll
    for (int h = 0; h < 12; h++) {
        float4 t = *(const float4*)&g_T[((size_t)(b * H_ + h) * S_ + j) * D_ + d0];
        Tc[h][0] = pack2(t.x * cvf.x, t.y * cvf.y);
        Tc[h][1] = pack2(t.z * cvf.z, t.w * cvf.w);
    }
    const float4 hvf = *(const float4*)&hidden[((size_t)(b * S_ + j)) * D_ + d0];
    const ull chv01 = pack2(hvf.x * cvf.x, hvf.y * cvf.y);
    const ull chv23 = pack2(hvf.z * cvf.z, hvf.w * cvf.w);
    const ull cc01  = pack2(cvf.x, cvf.y);
    const ull cc23  = pack2(cvf.z, cvf.w);

    __shared__ __align__(16) ull Pp[S_ * 12];     // 18.9 KB prepacked pairs
    __shared__ __align__(16) ull miw[S_][2];      // [i][0]=(is,is) [i][1]=(-m*is,-m*is)

    const ull* src = g_Pp + ((size_t)(b * S_ + j)) * S_ * 12;
    for (int idx = tid; idx < (S_ * 12) / 2; idx += 192)
        *(ulonglong2*)&Pp[idx * 2] = *(const ulonglong2*)&src[idx * 2];
    for (int t = tid; t < S_; t += 192) {
        float is = g_invstd[b * S_ + t];
        float m  = g_mean[(b * S_ + t) * S_ + j];
        float wv = -m * is;
        miw[t][0] = pack2(is, is);
        miw[t][1] = pack2(wv, wv);
    }
    __syncthreads();

    const int i0 = half ? 99 : 0;
    const int i1 = half ? S_ : 99;
    float* dst = &o_pl[((size_t)(b * S_ + i0) * S_ + j) * D_ + d0];
    for (int i = i0; i < i1; i++) {
        ull P[12];
        #pragma unroll
        for (int k = 0; k < 6; k++)
            *(ulonglong2*)&P[k * 2] = *(const ulonglong2*)&Pp[i * 12 + k * 2];
        ull acc0 = 0ull, acc1 = 0ull;         // acc = c * s
        #pragma unroll
        for (int h = 0; h < 12; h++) {
            fma2(acc0, P[h], Tc[h][0]);
            fma2(acc1, P[h], Tc[h][1]);
        }
        if (i == j) { acc0 = add2(acc0, chv01); acc1 = add2(acc1, chv23); }
        ulonglong2 mw = *(const ulonglong2*)&miw[i][0];   // .x=is2, .y=w2
        // o = acc*is + w*c
        ull o01 = mul2(cc01, mw.y);
        ull o23 = mul2(cc23, mw.y);
        fma2(o01, acc0, mw.x);
        fma2(o23, acc1, mw.x);
        __stcs((float2*)dst,       unpack2(o01));
        __stcs((float2*)(dst + 2), unpack2(o23));
        dst += (size_t)S_ * D_;
    }
}

// ---------------- mixing ratios + weighted_norm ----------------
__global__ __launch_bounds__(768)
void k_mixwn(const float* __restrict__ probs, const float* __restrict__ hidden,
             const float* __restrict__ lnw,
             float* __restrict__ m1, float* __restrict__ m2, float* __restrict__ m3,
             float* __restrict__ wn)
{
    const int blk = blockIdx.x;
    const int b = blk / S_, i = blk % S_;
    const int d = threadIdx.x;
    const int lane = d & 31, w = d >> 5;

    __shared__ float Pd[H_];
    __shared__ float red[5][24];
    __shared__ float bc[8];
    if (d < H_) Pd[d] = probs[((size_t)(b * H_ + d) * S_ + i) * S_ + i];
    __syncthreads();

    float sii = 0.f;
    #pragma unroll
    for (int h = 0; h < H_; h++)
        sii = fmaf(Pd[h], g_T[((size_t)(b * H_ + h) * S_ + i) * D_ + d], sii);

    size_t ridx = ((size_t)(b * S_ + i)) * D_ + d;
    float rs = 0.f;
    #pragma unroll
    for (int k = 0; k < KS_; k++) rs += g_rs[k][ridx];
    float hd   = hidden[ridx];
    float lw   = lnw[d];
    float mixv = rs - sii;
    float rwii = sii + hd;
    float rsrw = rs + hd;

    float a0 = wred(mixv * mixv);
    float a1 = wred(sii * sii);
    float a2 = wred(rwii * rwii);
    float a3 = wred(rwii);
    float a4 = wred(rsrw);
    if (lane == 0) {
        red[0][w] = a0; red[1][w] = a1; red[2][w] = a2;
        red[3][w] = a3; red[4][w] = a4;
    }
    __syncthreads();
    if (d < 5) {
        float sum = 0.f;
        #pragma unroll
        for (int k = 0; k < 24; k++) sum += red[d][k];
        bc[d] = sum;
    }
    __syncthreads();
    float mn1sq = bc[0], pn1sq = bc[1], pn2sq = bc[2];
    float mean_ii = bc[3] * (1.f / D_);
    float M       = bc[4] * (1.f / D_);
    float is = g_invstd[b * S_ + i];

    float pres3 = (rwii - mean_ii) * is * lw;
    float mix3  = is * lw * (rsrw - M) - pres3;
    float b0 = wred(pres3 * pres3);
    float b1 = wred(mix3 * mix3);
    if (lane == 0) { red[0][w] = b0; red[1][w] = b1; }
    __syncthreads();
    if (d == 0) {
        float B0 = 0.f, B1 = 0.f;
        #pragma unroll
        for (int k = 0; k < 24; k++) { B0 += red[0][k]; B1 += red[1][k]; }
        float mn1 = sqrtf(mn1sq), pn1 = sqrtf(pn1sq), pn2 = sqrtf(pn2sq);
        float pn3 = sqrtf(B0),   mn3 = sqrtf(B1);
        m1[b * S_ + i] = mn1 / (mn1 + pn1);
        m2[b * S_ + i] = mn1 / (mn1 + pn2);
        m3[b * S_ + i] = mn3 / (mn3 + pn3);
    }

    for (int idx = blk * 768 + d; idx < BH_ * SS_; idx += B_ * S_ * 768) {
        int bh = idx / SS_;
        int jj = idx % S_;
        __stcs(&wn[idx], probs[idx] * g_tnorm[bh * S_ + jj]);
    }
}

// ---------------- launch: fork/join two-stream graph ----------------
extern "C" void kernel_launch(void* const* d_in, const int* in_sizes, int n_in,
                              void* d_out, int out_size)
{
    const float* hidden = (const float*)d_in[0];
    const float* probs  = (const float*)d_in[1];
    const float* value  = (const float*)d_in[2];
    const float* dw     = (const float*)d_in[3];
    const float* lnw    = (const float*)d_in[4];
    const float* preln  = (const float*)d_in[5];

    float* out   = (float*)d_out;
    float* o_wn  = out;
    float* o_sn  = o_wn  + (size_t)BH_ * SS_;
    float* o_rwn = o_sn  + (size_t)B_ * SS_;
    float* o_pln = o_rwn + (size_t)B_ * SS_;
    float* o_pl  = o_pln + (size_t)B_ * SS_;
    float* o_m1  = o_pl  + (size_t)B_ * SS_ * D_;
    float* o_m2  = o_m1  + B_ * S_;
    float* o_m3  = o_m2  + B_ * S_;

    cudaStream_t s1;
    cudaStreamCreateWithFlags(&s1, cudaStreamNonBlocking);
    cudaEvent_t e0, e1, e2;
    cudaEventCreateWithFlags(&e0, cudaEventDisableTiming);
    cudaEventCreateWithFlags(&e1, cudaEventDisableTiming);
    cudaEventCreateWithFlags(&e2, cudaEventDisableTiming);

    // main (legacy) stream: k_tri -> k_rowsum -> (wait scal) k_mixwn -> (wait pl)
    k_tri<<<dim3(7, 6, BH_ + 1), 256>>>(value, dw, preln);
    cudaEventRecord(e0, 0);

    // side stream: k_scal -> k_pl
    cudaStreamWaitEvent(s1, e0, 0);
    k_scal<<<dim3(S_, B_), 256, 0, s1>>>(probs, hidden, lnw, o_sn, o_rwn, o_pln);
    cudaEventRecord(e1, s1);
    k_pl<<<dim3(S_, B_, 2), 192, 0, s1>>>(hidden, lnw, o_pl);
    cudaEventRecord(e2, s1);

    k_rowsum<<<dim3(7, 6, KS_ * B_), 256>>>(probs);
    cudaStreamWaitEvent(0, e1, 0);      // k_mixwn needs g_tnorm from k_scal
    k_mixwn<<<B_ * S_, 768>>>(probs, hidden, lnw, o_m1, o_m2, o_m3, o_wn);
    cudaStreamWaitEvent(0, e2, 0);      // join k_pl before capture end
}

// round 10
// speedup vs baseline: 4.9961x; 1.2299x over previous
#include <cuda_runtime.h>

#define B_   2
#define H_   12
#define S_   197
#define D_   768
#define HD_  64
#define SS_  (S_*S_)
#define BH_  (B_*H_)
#define LN_EPS 1e-12f
#define NPAIR 78
#define NDOT  209
#define KS2   4            // k-split for the C@W^T GEMM (192 k each)

typedef unsigned long long ull;

// ---------------- scratch (device globals; no allocation) ----------------
__device__ __align__(16) float g_T[BH_*S_*D_];
__device__ __align__(16) float g_tnorm[BH_*S_];
__device__ __align__(16) float g_C[(size_t)B_*S_*D_];      // C[b,i,h*64+v] = P@V
__device__ __align__(16) float g_rs[KS2][B_*S_*D_];        // rowsum partials
__device__ __align__(16) float g_invstd[B_*S_];
__device__ __align__(16) float g_mean[B_*SS_];
__device__ __align__(16) ull   g_Pp[(size_t)B_*SS_*12];    // P duplicated f32x2 pairs

__device__ __forceinline__ float wred(float x) {
    #pragma unroll
    for (int o = 16; o; o >>= 1) x += __shfl_xor_sync(0xffffffffu, x, o);
    return x;
}

// ---- packed f32x2 helpers ----
__device__ __forceinline__ ull pack2(float lo, float hi) {
    ull r;
    asm("mov.b64 %0, {%1, %2};" : "=l"(r) : "f"(lo), "f"(hi));
    return r;
}
__device__ __forceinline__ void fma2(ull& d, ull a, ull b) {
    asm("fma.rn.f32x2 %0, %1, %2, %0;" : "+l"(d) : "l"(a), "l"(b));
}
__device__ __forceinline__ ull mul2(ull a, ull b) {
    ull r;
    asm("mul.rn.f32x2 %0, %1, %2;" : "=l"(r) : "l"(a), "l"(b));
    return r;
}
__device__ __forceinline__ ull add2(ull a, ull b) {
    ull r;
    asm("add.rn.f32x2 %0, %1, %2;" : "=l"(r) : "l"(a), "l"(b));
    return r;
}
__device__ __forceinline__ float2 unpack2(ull v) {
    float2 f;
    asm("mov.b64 {%0, %1}, %2;" : "=f"(f.x), "=f"(f.y) : "l"(v));
    return f;
}

// ---------------- transformed GEMM + fused invstd ----------------
__global__ __launch_bounds__(256)
void k_tri(const float* __restrict__ V, const float* __restrict__ W,
           const float* __restrict__ preln)
{
    __shared__ __align__(16) float Vs[64][32];
    __shared__ __align__(16) float Ws[64][128];
    const int tid = threadIdx.x;

    if (blockIdx.z == BH_) {
        __shared__ float sh0[8], sh1[8];
        int q = blockIdx.x * 6 + blockIdx.y;
        for (int row = q; row < B_ * S_; row += 42) {
            const float* x = preln + (size_t)row * D_;
            float s = 0.f, s2 = 0.f;
            for (int d = tid; d < D_; d += 256) {
                float v = x[d];
                s += v; s2 += v * v;
            }
            s = wred(s); s2 = wred(s2);
            if ((tid & 31) == 0) { sh0[tid >> 5] = s; sh1[tid >> 5] = s2; }
            __syncthreads();
            if (tid == 0) {
                float S = 0.f, S2 = 0.f;
                #pragma unroll
                for (int w = 0; w < 8; w++) { S += sh0[w]; S2 += sh1[w]; }
                float mean = S * (1.f / D_);
                float var  = S2 * (1.f / D_) - mean * mean;
                g_invstd[row] = rsqrtf(var + LN_EPS);
            }
            __syncthreads();
        }
        return;
    }

    const int bh = blockIdx.z;
    const int h  = bh % H_;
    const int s0 = blockIdx.x * 32;
    const int d0 = blockIdx.y * 128;

    for (int idx = tid; idx < 64 * 32; idx += 256) {
        int v = idx >> 5, s = idx & 31;
        int gs = s0 + s;
        Vs[v][s] = (gs < S_) ? V[((size_t)bh * S_ + gs) * HD_ + v] : 0.f;
    }
    for (int idx = tid; idx < 64 * 128; idx += 256) {
        int v = idx >> 7, dd = idx & 127;
        Ws[v][dd] = W[(size_t)(d0 + dd) * D_ + h * HD_ + v];
    }
    __syncthreads();

    const int tx = tid & 31;
    const int ty = tid >> 5;
    ull acc[4][2] = {};
    #pragma unroll
    for (int v = 0; v < 64; v++) {
        float4 vv = *(const float4*)&Vs[v][ty * 4];
        float4 ww = *(const float4*)&Ws[v][tx * 4];
        ull t01 = pack2(ww.x, ww.y), t23 = pack2(ww.z, ww.w);
        ull a0 = pack2(vv.x, vv.x), a1 = pack2(vv.y, vv.y);
        ull a2 = pack2(vv.z, vv.z), a3 = pack2(vv.w, vv.w);
        fma2(acc[0][0], a0, t01); fma2(acc[0][1], a0, t23);
        fma2(acc[1][0], a1, t01); fma2(acc[1][1], a1, t23);
        fma2(acc[2][0], a2, t01); fma2(acc[2][1], a2, t23);
        fma2(acc[3][0], a3, t01); fma2(acc[3][1], a3, t23);
    }
    #pragma unroll
    for (int si = 0; si < 4; si++) {
        int s = s0 + ty * 4 + si;
        if (s < S_) {
            float2 lo = unpack2(acc[si][0]), hi = unpack2(acc[si][1]);
            float4 o = make_float4(lo.x, lo.y, hi.x, hi.y);
            *(float4*)&g_T[((size_t)bh * S_ + s) * D_ + d0 + tx * 4] = o;
        }
    }
}

// ---------------- k_pv: C[b,i,h*64+v] = sum_j P[b,h,i,j] V[b,h,j,v] ----------------
// grid (4, 1, 24): 64-i tiles x bh. 256 threads, 4i x 4v each.
__global__ __launch_bounds__(256)
void k_pv(const float* __restrict__ P, const float* __restrict__ V)
{
    const int bh = blockIdx.z;
    const int b  = bh / H_, h = bh % H_;
    const int i0 = blockIdx.x * 64;
    __shared__ __align__(16) float Ps[32][68];   // [j][i]
    __shared__ __align__(16) float Vs[32][64];   // [j][v]
    const int tid = threadIdx.x;
    const int tx = tid & 15, ty = tid >> 4;
    ull acc[4][2] = {};

    const float* Pb = P + (size_t)bh * SS_;
    const float* Vb = V + (size_t)bh * S_ * HD_;

    for (int j0 = 0; j0 < S_; j0 += 32) {
        #pragma unroll
        for (int it = 0; it < 8; it++) {
            int idx = tid + it * 256;
            int j = idx & 31, i = idx >> 5;
            int gi = i0 + i, gj = j0 + j;
            Ps[j][i] = (gi < S_ && gj < S_) ? Pb[(size_t)gi * S_ + gj] : 0.f;
        }
        #pragma unroll
        for (int it = 0; it < 2; it++) {
            int idx = tid + it * 256;
            int j = idx >> 4, vq = idx & 15;
            int gj = j0 + j;
            float4 v4 = (gj < S_) ? *(const float4*)&Vb[(size_t)gj * HD_ + vq * 4]
                                  : make_float4(0.f, 0.f, 0.f, 0.f);
            *(float4*)&Vs[j][vq * 4] = v4;
        }
        __syncthreads();
        #pragma unroll 8
        for (int j = 0; j < 32; j++) {
            float4 pv = *(const float4*)&Ps[j][ty * 4];
            float4 vv = *(const float4*)&Vs[j][tx * 4];
            ull t01 = pack2(vv.x, vv.y), t23 = pack2(vv.z, vv.w);
            ull a0 = pack2(pv.x, pv.x), a1 = pack2(pv.y, pv.y);
            ull a2 = pack2(pv.z, pv.z), a3 = pack2(pv.w, pv.w);
            fma2(acc[0][0], a0, t01); fma2(acc[0][1], a0, t23);
            fma2(acc[1][0], a1, t01); fma2(acc[1][1], a1, t23);
            fma2(acc[2][0], a2, t01); fma2(acc[2][1], a2, t23);
            fma2(acc[3][0], a3, t01); fma2(acc[3][1], a3, t23);
        }
        __syncthreads();
    }
    #pragma unroll
    for (int si = 0; si < 4; si++) {
        int gi = i0 + ty * 4 + si;
        if (gi < S_) {
            float2 lo = unpack2(acc[si][0]), hi = unpack2(acc[si][1]);
            float4 o = make_float4(lo.x, lo.y, hi.x, hi.y);
            *(float4*)&g_C[((size_t)(b * S_ + gi)) * D_ + h * HD_ + tx * 4] = o;
        }
    }
}

// ---------------- k_cw: rowsum[m,n] = sum_k C[m,k] W[n,k], k-split ----------------
// grid (13, 6, KS2): 32-m x 128-n tiles, 192-k chunks. 256 threads, 4m x 4n.
__global__ __launch_bounds__(256)
void k_cw(const float* __restrict__ W)
{
    const int m0 = blockIdx.x * 32;
    const int n0 = blockIdx.y * 128;
    const int split = blockIdx.z;
    __shared__ __align__(16) float Cs[32][36];    // [k][m]
    __shared__ __align__(16) float Ws[32][132];   // [k][n]
    const int tid = threadIdx.x;
    const int tx = tid & 31, ty = tid >> 5;
    ull acc[4][2] = {};

    for (int kk = 0; kk < 192; kk += 32) {
        const int k0 = split * 192 + kk;
        {
            int m = tid >> 3, kq = tid & 7;
            int gm = m0 + m;
            float4 c4 = (gm < B_ * S_) ? *(const float4*)&g_C[(size_t)gm * D_ + k0 + kq * 4]
                                       : make_float4(0.f, 0.f, 0.f, 0.f);
            Cs[kq * 4 + 0][m] = c4.x; Cs[kq * 4 + 1][m] = c4.y;
            Cs[kq * 4 + 2][m] = c4.z; Cs[kq * 4 + 3][m] = c4.w;
        }
        #pragma unroll
        for (int it = 0; it < 4; it++) {
            int idx = tid + it * 256;
            int n = idx >> 3, kq = idx & 7;
            float4 w4 = *(const float4*)&W[(size_t)(n0 + n) * D_ + k0 + kq * 4];
            Ws[kq * 4 + 0][n] = w4.x; Ws[kq * 4 + 1][n] = w4.y;
            Ws[kq * 4 + 2][n] = w4.z; Ws[kq * 4 + 3][n] = w4.w;
        }
        __syncthreads();
        #pragma unroll 8
        for (int k = 0; k < 32; k++) {
            float4 cm = *(const float4*)&Cs[k][ty * 4];
            float4 wn = *(const float4*)&Ws[k][tx * 4];
            ull t01 = pack2(wn.x, wn.y), t23 = pack2(wn.z, wn.w);
            ull a0 = pack2(cm.x, cm.x), a1 = pack2(cm.y, cm.y);
            ull a2 = pack2(cm.z, cm.z), a3 = pack2(cm.w, cm.w);
            fma2(acc[0][0], a0, t01); fma2(acc[0][1], a0, t23);
            fma2(acc[1][0], a1, t01); fma2(acc[1][1], a1, t23);
            fma2(acc[2][0], a2, t01); fma2(acc[2][1], a2, t23);
            fma2(acc[3][0], a3, t01); fma2(acc[3][1], a3, t23);
        }
        __syncthreads();
    }
    #pragma unroll
    for (int si = 0; si < 4; si++) {
        int gm = m0 + ty * 4 + si;
        if (gm < B_ * S_) {
            float2 lo = unpack2(acc[si][0]), hi = unpack2(acc[si][1]);
            float4 o = make_float4(lo.x, lo.y, hi.x, hi.y);
            *(float4*)&g_rs[split][(size_t)gm * D_ + n0 + tx * 4] = o;
        }
    }
}

// ---------------- scalar kernel: Gram matrices + all per-(i,j) scalars ----------------
__global__ __launch_bounds__(256)
void k_scal(const float* __restrict__ probs, const float* __restrict__ hidden,
            const float* __restrict__ lnw,
            float* __restrict__ o_sn, float* __restrict__ o_rwn,
            float* __restrict__ o_pln)
{
    const int j = blockIdx.x, b = blockIdx.y;
    const int tid = threadIdx.x;
    const int lane = tid & 31, w = tid >> 5;

    __shared__ float part[NDOT * 8];
    __shared__ float dsm[NDOT];
    __shared__ float Psh[S_ * 13];

    float T[12][3], hd[3], c2[3];
    #pragma unroll
    for (int h = 0; h < 12; h++) {
        const float* tp = g_T + ((size_t)(b * H_ + h) * S_ + j) * D_ + tid;
        #pragma unroll
        for (int k = 0; k < 3; k++) T[h][k] = tp[k * 256];
    }
    {
        const float* hp = hidden + ((size_t)(b * S_ + j)) * D_ + tid;
        const float* cp = lnw + tid;
        #pragma unroll
        for (int k = 0; k < 3; k++) {
            hd[k] = hp[k * 256];
            float c = cp[k * 256];
            c2[k] = c * c;
        }
    }

    const size_t pbase = ((size_t)(b * S_ + j)) * S_ * 12;
    for (int idx = tid; idx < H_ * S_; idx += 256) {
        int i = idx / 12, h = idx % 12;
        float v = probs[((size_t)(b * H_ + h) * S_ + i) * S_ + j];
        Psh[i * 13 + h] = v;
        g_Pp[pbase + idx] = pack2(v, v);
    }

    {
        int p = 0;
        #pragma unroll
        for (int h = 0; h < 12; h++) {
            #pragma unroll
            for (int h2 = h; h2 < 12; h2++) {
                float q0 = T[h][0] * T[h2][0];
                float q1 = T[h][1] * T[h2][1];
                float q2 = T[h][2] * T[h2][2];
                float g1 = q0 + q1 + q2;
                float g2 = c2[0] * q0 + c2[1] * q1 + c2[2] * q2;
                g1 = wred(g1); g2 = wred(g2);
                if (lane == 0) {
                    part[p * 8 + w]           = g1;
                    part[(NPAIR + p) * 8 + w] = g2;
                }
                p++;
            }
        }
    }
    #pragma unroll
    for (int h = 0; h < 12; h++) {
        float u1 = T[h][0] + T[h][1] + T[h][2];
        float u2 = c2[0] * T[h][0] + c2[1] * T[h][1] + c2[2] * T[h][2];
        float q0 = T[h][0] * hd[0], q1 = T[h][1] * hd[1], q2 = T[h][2] * hd[2];
        float v1 = q0 + q1 + q2;
        float v2 = c2[0] * q0 + c2[1] * q1 + c2[2] * q2;
        u1 = wred(u1); u2 = wred(u2); v1 = wred(v1); v2 = wred(v2);
        if (lane == 0) {
            part[(156 + h) * 8 + w] = u1;
            part[(168 + h) * 8 + w] = u2;
            part[(180 + h) * 8 + w] = v1;
            part[(192 + h) * 8 + w] = v2;
        }
    }
    {
        float e0 = 0.f, e1 = 0.f, e2 = 0.f, e3 = 0.f, cs = 0.f;
        #pragma unroll
        for (int k = 0; k < 3; k++) {
            e0 += hd[k] * hd[k];
            e1 += hd[k];
            e2 += c2[k] * hd[k];
            e3 += c2[k] * hd[k] * hd[k];
            cs += c2[k];
        }
        e0 = wred(e0); e1 = wred(e1); e2 = wred(e2); e3 = wred(e3); cs = wred(cs);
        if (lane == 0) {
            part[204 * 8 + w] = e0; part[205 * 8 + w] = e1;
            part[206 * 8 + w] = e2; part[207 * 8 + w] = e3;
            part[208 * 8 + w] = cs;
        }
    }
    __syncthreads();
    if (tid < NDOT) {
        float s = 0.f;
        #pragma unroll
        for (int k = 0; k < 8; k++) s += part[tid * 8 + k];
        dsm[tid] = s;
    }
    __syncthreads();

    if (tid < 12) {
        int h = tid;
        int pd = h * 12 - (h * (h - 1)) / 2;
        g_tnorm[(b * H_ + h) * S_ + j] = sqrtf(fmaxf(dsm[pd], 0.f));
    }

    if (tid < S_) {
        int i = tid;
        float P[12];
        #pragma unroll
        for (int h = 0; h < 12; h++) P[h] = Psh[i * 13 + h];

        float n1 = 0.f, n3 = 0.f;
        {
            int p = 0;
            #pragma unroll
            for (int h = 0; h < 12; h++) {
                float ph = P[h];
                n1 = fmaf(ph * ph, dsm[p], n1);
                n3 = fmaf(ph * ph, dsm[NPAIR + p], n3);
                p++;
                #pragma unroll
                for (int h2 = h + 1; h2 < 12; h2++) {
                    float pp = 2.f * ph * P[h2];
                    n1 = fmaf(pp, dsm[p], n1);
                    n3 = fmaf(pp, dsm[NPAIR + p], n3);
                    p++;
                }
            }
        }
        float sum_s = 0.f, L = 0.f, sv1 = 0.f, sv2 = 0.f;
        #pragma unroll
        for (int h = 0; h < 12; h++) {
            sum_s = fmaf(P[h], dsm[156 + h], sum_s);
            L     = fmaf(P[h], dsm[168 + h], L);
            sv1   = fmaf(P[h], dsm[180 + h], sv1);
            sv2   = fmaf(P[h], dsm[192 + h], sv2);
        }
        float n2 = n1, Ssum = sum_s, a3 = L, a4 = n3;
        if (i == j) {
            n2   += 2.f * sv1 + dsm[204];
            Ssum += dsm[205];
            a3   += dsm[206];
            a4   += 2.f * sv2 + dsm[207];
        }
        float mean = Ssum * (1.f / D_);
        float is = g_invstd[b * S_ + i];
        int o = (b * S_ + i) * S_ + j;
        o_sn[o]  = sqrtf(fmaxf(n1, 0.f));
        o_rwn[o] = sqrtf(fmaxf(n2, 0.f));
        float pn2 = is * is * (a4 - 2.f * mean * a3 + mean * mean * dsm[208]);
        o_pln[o] = sqrtf(fmaxf(pn2, 0.f));
        g_mean[o] = mean;
    }
}

// ---------------- post_ln elementwise: block = (j, b, half), 192 thr x 4 d ----------------
__global__ __launch_bounds__(192)
void k_pl(const float* __restrict__ hidden, const float* __restrict__ lnw,
          float* __restrict__ o_pl)
{
    const int j = blockIdx.x, b = blockIdx.y, half = blockIdx.z;
    const int tid = threadIdx.x;
    const int d0 = tid * 4;

    const float4 cvf = *(const float4*)&lnw[d0];
    ull Tc[12][2];
    #pragma unroll
    for (int h = 0; h < 12; h++) {
        float4 t = *(const float4*)&g_T[((size_t)(b * H_ + h) * S_ + j) * D_ + d0];
        Tc[h][0] = pack2(t.x * cvf.x, t.y * cvf.y);
        Tc[h][1] = pack2(t.z * cvf.z, t.w * cvf.w);
    }
    const float4 hvf = *(const float4*)&hidden[((size_t)(b * S_ + j)) * D_ + d0];
    const ull chv01 = pack2(hvf.x * cvf.x, hvf.y * cvf.y);
    const ull chv23 = pack2(hvf.z * cvf.z, hvf.w * cvf.w);
    const ull cc01  = pack2(cvf.x, cvf.y);
    const ull cc23  = pack2(cvf.z, cvf.w);

    __shared__ __align__(16) ull Pp[S_ * 12];
    __shared__ __align__(16) ull miw[S_][2];

    const ull* src = g_Pp + ((size_t)(b * S_ + j)) * S_ * 12;
    for (int idx = tid; idx < (S_ * 12) / 2; idx += 192)
        *(ulonglong2*)&Pp[idx * 2] = *(const ulonglong2*)&src[idx * 2];
    for (int t = tid; t < S_; t += 192) {
        float is = g_invstd[b * S_ + t];
        float m  = g_mean[(b * S_ + t) * S_ + j];
        float wv = -m * is;
        miw[t][0] = pack2(is, is);
        miw[t][1] = pack2(wv, wv);
    }
    __syncthreads();

    const int i0 = half ? 99 : 0;
    const int i1 = half ? S_ : 99;
    float* dst = &o_pl[((size_t)(b * S_ + i0) * S_ + j) * D_ + d0];
    for (int i = i0; i < i1; i++) {
        ull P[12];
        #pragma unroll
        for (int k = 0; k < 6; k++)
            *(ulonglong2*)&P[k * 2] = *(const ulonglong2*)&Pp[i * 12 + k * 2];
        ull acc0 = 0ull, acc1 = 0ull;
        #pragma unroll
        for (int h = 0; h < 12; h++) {
            fma2(acc0, P[h], Tc[h][0]);
            fma2(acc1, P[h], Tc[h][1]);
        }
        if (i == j) { acc0 = add2(acc0, chv01); acc1 = add2(acc1, chv23); }
        ulonglong2 mw = *(const ulonglong2*)&miw[i][0];
        ull o01 = mul2(cc01, mw.y);
        ull o23 = mul2(cc23, mw.y);
        fma2(o01, acc0, mw.x);
        fma2(o23, acc1, mw.x);
        __stcs((float2*)dst,       unpack2(o01));
        __stcs((float2*)(dst + 2), unpack2(o23));
        dst += (size_t)S_ * D_;
    }
}

// ---------------- mixing ratios + weighted_norm ----------------
__global__ __launch_bounds__(768)
void k_mixwn(const float* __restrict__ probs, const float* __restrict__ hidden,
             const float* __restrict__ lnw,
             float* __restrict__ m1, float* __restrict__ m2, float* __restrict__ m3,
             float* __restrict__ wn)
{
    const int blk = blockIdx.x;
    const int b = blk / S_, i = blk % S_;
    const int d = threadIdx.x;
    const int lane = d & 31, w = d >> 5;

    __shared__ float Pd[H_];
    __shared__ float red[5][24];
    __shared__ float bc[8];
    if (d < H_) Pd[d] = probs[((size_t)(b * H_ + d) * S_ + i) * S_ + i];
    __syncthreads();

    float sii = 0.f;
    #pragma unroll
    for (int h = 0; h < H_; h++)
        sii = fmaf(Pd[h], g_T[((size_t)(b * H_ + h) * S_ + i) * D_ + d], sii);

    size_t ridx = ((size_t)(b * S_ + i)) * D_ + d;
    float rs = 0.f;
    #pragma unroll
    for (int k = 0; k < KS2; k++) rs += g_rs[k][ridx];
    float hd   = hidden[ridx];
    float lw   = lnw[d];
    float mixv = rs - sii;
    float rwii = sii + hd;
    float rsrw = rs + hd;

    float a0 = wred(mixv * mixv);
    float a1 = wred(sii * sii);
    float a2 = wred(rwii * rwii);
    float a3 = wred(rwii);
    float a4 = wred(rsrw);
    if (lane == 0) {
        red[0][w] = a0; red[1][w] = a1; red[2][w] = a2;
        red[3][w] = a3; red[4][w] = a4;
    }
    __syncthreads();
    if (d < 5) {
        float sum = 0.f;
        #pragma unroll
        for (int k = 0; k < 24; k++) sum += red[d][k];
        bc[d] = sum;
    }
    __syncthreads();
    float mn1sq = bc[0], pn1sq = bc[1], pn2sq = bc[2];
    float mean_ii = bc[3] * (1.f / D_);
    float M       = bc[4] * (1.f / D_);
    float is = g_invstd[b * S_ + i];

    float pres3 = (rwii - mean_ii) * is * lw;
    float mix3  = is * lw * (rsrw - M) - pres3;
    float b0 = wred(pres3 * pres3);
    float b1 = wred(mix3 * mix3);
    if (lane == 0) { red[0][w] = b0; red[1][w] = b1; }
    __syncthreads();
    if (d == 0) {
        float B0 = 0.f, B1 = 0.f;
        #pragma unroll
        for (int k = 0; k < 24; k++) { B0 += red[0][k]; B1 += red[1][k]; }
        float mn1 = sqrtf(mn1sq), pn1 = sqrtf(pn1sq), pn2 = sqrtf(pn2sq);
        float pn3 = sqrtf(B0),   mn3 = sqrtf(B1);
        m1[b * S_ + i] = mn1 / (mn1 + pn1);
        m2[b * S_ + i] = mn1 / (mn1 + pn2);
        m3[b * S_ + i] = mn3 / (mn3 + pn3);
    }

    for (int idx = blk * 768 + d; idx < BH_ * SS_; idx += B_ * S_ * 768) {
        int bh = idx / SS_;
        int jj = idx % S_;
        __stcs(&wn[idx], probs[idx] * g_tnorm[bh * S_ + jj]);
    }
}

// ---------------- launch: two-stream DAG ----------------
extern "C" void kernel_launch(void* const* d_in, const int* in_sizes, int n_in,
                              void* d_out, int out_size)
{
    const float* hidden = (const float*)d_in[0];
    const float* probs  = (const float*)d_in[1];
    const float* value  = (const float*)d_in[2];
    const float* dw     = (const float*)d_in[3];
    const float* lnw    = (const float*)d_in[4];
    const float* preln  = (const float*)d_in[5];

    float* out   = (float*)d_out;
    float* o_wn  = out;
    float* o_sn  = o_wn  + (size_t)BH_ * SS_;
    float* o_rwn = o_sn  + (size_t)B_ * SS_;
    float* o_pln = o_rwn + (size_t)B_ * SS_;
    float* o_pl  = o_pln + (size_t)B_ * SS_;
    float* o_m1  = o_pl  + (size_t)B_ * SS_ * D_;
    float* o_m2  = o_m1  + B_ * S_;
    float* o_m3  = o_m2  + B_ * S_;

    cudaStream_t s1;
    cudaStreamCreateWithFlags(&s1, cudaStreamNonBlocking);
    cudaEvent_t e0, e1, e2;
    cudaEventCreateWithFlags(&e0, cudaEventDisableTiming);
    cudaEventCreateWithFlags(&e1, cudaEventDisableTiming);
    cudaEventCreateWithFlags(&e2, cudaEventDisableTiming);

    // fork before any work: side stream runs the input-only rowsum chain
    cudaEventRecord(e0, 0);
    cudaStreamWaitEvent(s1, e0, 0);
    k_pv<<<dim3(4, 1, BH_), 256, 0, s1>>>(probs, value);
    k_cw<<<dim3(13, 6, KS2), 256, 0, s1>>>(dw);

    // main stream: T/invstd -> scal -> pl
    k_tri<<<dim3(7, 6, BH_ + 1), 256>>>(value, dw, preln);
    k_scal<<<dim3(S_, B_), 256>>>(probs, hidden, lnw, o_sn, o_rwn, o_pln);
    cudaEventRecord(e1, 0);
    k_pl<<<dim3(S_, B_, 2), 192>>>(hidden, lnw, o_pl);

    // mixwn on s1: needs rowsum (s1) + g_T/tnorm/invstd (via e1)
    cudaStreamWaitEvent(s1, e1, 0);
    k_mixwn<<<B_ * S_, 768, 0, s1>>>(probs, hidden, lnw, o_m1, o_m2, o_m3, o_wn);
    cudaEventRecord(e2, s1);
    cudaStreamWaitEvent(0, e2, 0);
}